// round 13
// baseline (speedup 1.0000x reference)
#include <cuda_runtime.h>

// ---------------------------------------------------------------------------
// Problem constants
// ---------------------------------------------------------------------------
#define NTOK    294
#define NPAD    304            // padded tokens (19 * 16)
#define NT16    19
#define NWIN    288
#define D_MODEL 256
#define HEADS   8
#define DH      32
#define M_ROWS  (NWIN * NTOK)  // 84672
#define QKV_N   768

// smem strides (floats), conflict-free for the tf32 fragment access patterns
#define QS   36   // K rows (32 cols): banks 4g+t bijective
#define VS   40   // V rows (32 cols): banks 8t+g bijective
#define BS2  136  // GEMM B tile rows (128 cols): banks 8t+g bijective

// ---------------------------------------------------------------------------
// Scratch
// ---------------------------------------------------------------------------
__device__ float g_q   [(size_t)NWIN * HEADS * NTOK * DH];
__device__ float g_k   [(size_t)NWIN * HEADS * NTOK * DH];
__device__ float g_v   [(size_t)NWIN * HEADS * NTOK * DH];
__device__ float g_ctx [(size_t)M_ROWS * D_MODEL];
__device__ float g_wqkv[256 * 768];   // [k][n], tf32 bits
__device__ float g_wout[256 * 256];   // [k][n], tf32 bits

__device__ __forceinline__ int x_offset(int r) {
    int w  = r / NTOK;  int t   = r - w * NTOK;
    int bb = w / 144;   int rem = w - bb * 144;
    int gx = rem / 12;  int gy  = rem - gx * 12;
    int l  = t / 49;    int t2  = t - l * 49;
    int w1 = t2 / 7;    int w2  = t2 - w1 * 7;
    return (((((bb * 6 + l) * 12 + gx) * 12 + gy) * 7 + w1) * 7 + w2) * D_MODEL;
}

__device__ __forceinline__ unsigned f2tf(float f) {
    unsigned u;
    asm("cvt.rna.tf32.f32 %0, %1;" : "=r"(u) : "f"(f));
    return u;
}
__device__ __forceinline__ unsigned fbits(float f) { return __float_as_uint(f); }

__device__ __forceinline__ void mma_tf32(float c[4], const unsigned a[4], const unsigned b[2]) {
    asm volatile(
        "mma.sync.aligned.m16n8k8.row.col.f32.tf32.tf32.f32 "
        "{%0,%1,%2,%3}, {%4,%5,%6,%7}, {%8,%9}, {%0,%1,%2,%3};"
        : "+f"(c[0]), "+f"(c[1]), "+f"(c[2]), "+f"(c[3])
        : "r"(a[0]), "r"(a[1]), "r"(a[2]), "r"(a[3]), "r"(b[0]), "r"(b[1]));
}

__device__ __forceinline__ void cp16(unsigned dst, const void* src) {
    asm volatile("cp.async.cg.shared.global [%0], [%1], 16;" :: "r"(dst), "l"(src));
}
__device__ __forceinline__ void cp_commit() {
    asm volatile("cp.async.commit_group;" ::);
}
__device__ __forceinline__ void cp_wait0() {
    asm volatile("cp.async.wait_group 0;" ::: "memory");
}

// ===========================================================================
// Kernel 0: one-time weight conversion to tf32 ([k][n] layouts).
// ===========================================================================
__global__ __launch_bounds__(256) void conv_w(
    const float* __restrict__ Wq, const float* __restrict__ Wkv,
    const float* __restrict__ Wout)
{
    int idx = blockIdx.x * 256 + threadIdx.x;
    if (idx < 256 * 768) {
        int k = idx / 768, n = idx - k * 768;
        float v = (n < 256) ? Wq[k * 256 + n] : Wkv[k * 512 + (n - 256)];
        g_wqkv[idx] = __uint_as_float(f2tf(v));
    }
    if (idx < 256 * 256) {
        g_wout[idx] = __uint_as_float(f2tf(Wout[idx]));
    }
}

// ===========================================================================
// Kernel 1: QKV projection. CTA 64x128, 4 warps of 32x64, BK=32.
// cp.async double-buffer: no register round-trip, ~110 regs -> 4 CTAs/SM.
// x staged RAW (HMMA truncates to tf32); weights pre-rounded.
// ===========================================================================
__global__ __launch_bounds__(128) void qkv_gemm_tc(
    const float* __restrict__ x,
    const float* __restrict__ bq, const float* __restrict__ bkv)
{
    __shared__ float As[2][64 * QS];
    __shared__ float Bs[2][32 * BS2];
    __shared__ int   rowbase[64];

    const int tid  = threadIdx.x;
    const int lane = tid & 31, wid = tid >> 5;
    const int wm = wid & 1, wn = wid >> 1;
    const int g = lane >> 2, t = lane & 3;
    const int r0 = blockIdx.y * 64;      // row block (slow dim)
    const int c0 = blockIdx.x * 128;     // col block (fast dim)

    if (tid < 64) rowbase[tid] = x_offset(r0 + tid);
    __syncthreads();

    const float* asrc[4]; unsigned adst[4];
    const float* bsrc[8]; unsigned bdst[8];
#pragma unroll
    for (int i = 0; i < 4; i++) {
        int idx = tid + i * 128;
        int ar = idx >> 3, aq = idx & 7;
        asrc[i] = x + rowbase[ar] + aq * 4;
        adst[i] = (unsigned)__cvta_generic_to_shared(&As[0][ar * QS + aq * 4]);
    }
#pragma unroll
    for (int i = 0; i < 8; i++) {
        int idx = tid + i * 128;
        int bk = idx >> 5, bc = idx & 31;
        bsrc[i] = g_wqkv + bk * QKV_N + c0 + bc * 4;
        bdst[i] = (unsigned)__cvta_generic_to_shared(&Bs[0][bk * BS2 + bc * 4]);
    }
    const unsigned ABYTES = 64 * QS * 4;
    const unsigned BBYTES = 32 * BS2 * 4;

    float acc[2][8][4];
#pragma unroll
    for (int m = 0; m < 2; m++)
#pragma unroll
        for (int n = 0; n < 8; n++)
#pragma unroll
            for (int e = 0; e < 4; e++) acc[m][n][e] = 0.f;

#pragma unroll
    for (int i = 0; i < 4; i++) cp16(adst[i], asrc[i]);
#pragma unroll
    for (int i = 0; i < 8; i++) cp16(bdst[i], bsrc[i]);
    cp_commit();

    for (int it = 0; it < 8; it++) {
        const int cur = it & 1;
        cp_wait0();
        __syncthreads();
        if (it < 7) {
            const int k0 = (it + 1) * 32;
            const unsigned nb = (it + 1) & 1;
#pragma unroll
            for (int i = 0; i < 4; i++) cp16(adst[i] + nb * ABYTES, asrc[i] + k0);
#pragma unroll
            for (int i = 0; i < 8; i++) cp16(bdst[i] + nb * BBYTES, bsrc[i] + (size_t)k0 * QKV_N);
            cp_commit();
        }
#pragma unroll
        for (int kk = 0; kk < 4; kk++) {
            unsigned afr[2][4];
#pragma unroll
            for (int mt = 0; mt < 2; mt++) {
                int mr = wm * 32 + mt * 16;
                afr[mt][0] = fbits(As[cur][(mr + g)     * QS + kk * 8 + t]);
                afr[mt][1] = fbits(As[cur][(mr + g + 8) * QS + kk * 8 + t]);
                afr[mt][2] = fbits(As[cur][(mr + g)     * QS + kk * 8 + t + 4]);
                afr[mt][3] = fbits(As[cur][(mr + g + 8) * QS + kk * 8 + t + 4]);
            }
#pragma unroll
            for (int nt = 0; nt < 8; nt++) {
                int nc = wn * 64 + nt * 8;
                unsigned bfr[2];
                bfr[0] = fbits(Bs[cur][(kk * 8 + t)     * BS2 + nc + g]);
                bfr[1] = fbits(Bs[cur][(kk * 8 + t + 4) * BS2 + nc + g]);
                mma_tf32(acc[0][nt], afr[0], bfr);
                mma_tf32(acc[1][nt], afr[1], bfr);
            }
        }
    }

    const float scale = 0.17677669529663687f;
#pragma unroll
    for (int mt = 0; mt < 2; mt++) {
#pragma unroll
        for (int e = 0; e < 2; e++) {
            int r = r0 + wm * 32 + mt * 16 + g + e * 8;
            int w = r / NTOK;  int tok = r - w * NTOK;
#pragma unroll
            for (int nt = 0; nt < 8; nt++) {
                int nc = c0 + wn * 64 + nt * 8 + 2 * t;     // even; pair {nc, nc+1}
                float va0 = acc[mt][nt][e * 2 + 0];
                float va1 = acc[mt][nt][e * 2 + 1];
                if (nc < D_MODEL) {
                    int h = nc >> 5, c = nc & 31;
                    float2 v2 = make_float2(
                        __uint_as_float(f2tf((va0 + __ldg(bq + nc))     * scale)),
                        __uint_as_float(f2tf((va1 + __ldg(bq + nc + 1)) * scale)));
                    *(float2*)(g_q + (((size_t)w * HEADS + h) * NTOK + tok) * DH + c) = v2;
                } else {
                    int kc = nc - D_MODEL;
                    float2 v2 = make_float2(
                        __uint_as_float(f2tf(va0 + __ldg(bkv + kc))),
                        __uint_as_float(f2tf(va1 + __ldg(bkv + kc + 1))));
                    if (kc < D_MODEL) {
                        int h = kc >> 5, c = kc & 31;
                        *(float2*)(g_k + (((size_t)w * HEADS + h) * NTOK + tok) * DH + c) = v2;
                    } else {
                        int vc = kc - D_MODEL;
                        int h = vc >> 5, c = vc & 31;
                        *(float2*)(g_v + (((size_t)w * HEADS + h) * NTOK + tok) * DH + c) = v2;
                    }
                }
            }
        }
    }
}

// ===========================================================================
// Kernel 2: register-resident flash attention. 320 threads = 10 warps,
// exactly ONE tile-pair per warp (perfect balance, single pass).
// Bias loads software-pipelined out of the exp critical chain.
// ===========================================================================
__global__ __launch_bounds__(320, 2) void attn_flash(const float* __restrict__ bias_table)
{
    extern __shared__ float sm[];
    float* Ks = sm;                       // NPAD x 36
    float* Vs = sm + NPAD * QS;           // NPAD x 40
    int*   bJ = (int*)(Vs + NPAD * VS);   // NPAD

    const int wh = blockIdx.x;
    const int w  = wh >> 3, h = wh & 7;
    const int tid = threadIdx.x;
    const int lane = tid & 31, wid = tid >> 5;
    const int g = lane >> 2, t = lane & 3;

    const float* kg = g_k + (size_t)wh * NTOK * DH;
    const float* vg = g_v + (size_t)wh * NTOK * DH;
    for (int idx = tid; idx < NTOK * 8; idx += 320) {
        int row = idx >> 3, q4 = (idx & 7) * 4;
        *(float4*)(Ks + row * QS + q4) = *(const float4*)(kg + row * DH + q4);
        *(float4*)(Vs + row * VS + q4) = *(const float4*)(vg + row * DH + q4);
    }
    for (int idx = tid; idx < (NPAD - NTOK) * 8; idx += 320) {
        int row = NTOK + (idx >> 3), q4 = (idx & 7) * 4;
        float4 z = make_float4(0.f, 0.f, 0.f, 0.f);
        *(float4*)(Ks + row * QS + q4) = z;
        *(float4*)(Vs + row * VS + q4) = z;
    }
    for (int j = tid; j < NPAD; j += 320) {
        int jj = min(j, NTOK - 1);
        int l = jj / 49, r2 = jj - l * 49, a = r2 / 7, b = r2 - a * 7;
        bJ[j] = l * 169 + a * 13 + b;
    }
    __syncthreads();

    const float* qg = g_q + (size_t)wh * NTOK * DH;

    // one pair per warp: warp wid covers tiles (2*wid, min(2*wid+1, 18))
    {
        const int p   = wid;              // 0..9
        const int mtA = 2 * p;
        const int mtB = min(2 * p + 1, NT16 - 1);

        const int rA0 = mtA * 16 + g, rA1 = rA0 + 8;
        const int rB0 = mtB * 16 + g, rB1 = rB0 + 8;
        const int cA0 = min(rA0, NTOK - 1), cA1 = min(rA1, NTOK - 1);
        const int cB0 = min(rB0, NTOK - 1), cB1 = min(rB1, NTOK - 1);

        int CiA0, CiA1, CiB0, CiB1;
        {
            int l, r2, a, b;
            l = cA0 / 49; r2 = cA0 - l * 49; a = r2 / 7; b = r2 - a * 7;
            CiA0 = (l + 5) * 169 + (a + 6) * 13 + (b + 6);
            l = cA1 / 49; r2 = cA1 - l * 49; a = r2 / 7; b = r2 - a * 7;
            CiA1 = (l + 5) * 169 + (a + 6) * 13 + (b + 6);
            l = cB0 / 49; r2 = cB0 - l * 49; a = r2 / 7; b = r2 - a * 7;
            CiB0 = (l + 5) * 169 + (a + 6) * 13 + (b + 6);
            l = cB1 / 49; r2 = cB1 - l * 49; a = r2 / 7; b = r2 - a * 7;
            CiB1 = (l + 5) * 169 + (a + 6) * 13 + (b + 6);
        }

        unsigned qaA[4][4], qaB[4][4];
#pragma unroll
        for (int kk = 0; kk < 4; kk++) {
            qaA[kk][0] = fbits(__ldg(qg + cA0 * DH + kk * 8 + t));
            qaA[kk][1] = fbits(__ldg(qg + cA1 * DH + kk * 8 + t));
            qaA[kk][2] = fbits(__ldg(qg + cA0 * DH + kk * 8 + t + 4));
            qaA[kk][3] = fbits(__ldg(qg + cA1 * DH + kk * 8 + t + 4));
            qaB[kk][0] = fbits(__ldg(qg + cB0 * DH + kk * 8 + t));
            qaB[kk][1] = fbits(__ldg(qg + cB1 * DH + kk * 8 + t));
            qaB[kk][2] = fbits(__ldg(qg + cB0 * DH + kk * 8 + t + 4));
            qaB[kk][3] = fbits(__ldg(qg + cB1 * DH + kk * 8 + t + 4));
        }

        float OA[4][4], OB[4][4];
#pragma unroll
        for (int ot = 0; ot < 4; ot++)
#pragma unroll
            for (int e = 0; e < 4; e++) { OA[ot][e] = 0.f; OB[ot][e] = 0.f; }
        float sA0 = 0.f, sA1 = 0.f, sB0 = 0.f, sB1 = 0.f;

        const int src1 = (lane & 28) | (t >> 1);
        const int src2 = src1 + 2;

        // bias prefetch for nt = 0
        float bc[8];
        {
            int j0 = 2 * t, j1 = j0 + 1;
            int bj0 = bJ[j0], bj1 = bJ[j1];
            bc[0] = __ldg(bias_table + (size_t)(CiA0 - bj0) * HEADS + h);
            bc[1] = __ldg(bias_table + (size_t)(CiA0 - bj1) * HEADS + h);
            bc[2] = __ldg(bias_table + (size_t)(CiA1 - bj0) * HEADS + h);
            bc[3] = __ldg(bias_table + (size_t)(CiA1 - bj1) * HEADS + h);
            bc[4] = __ldg(bias_table + (size_t)(CiB0 - bj0) * HEADS + h);
            bc[5] = __ldg(bias_table + (size_t)(CiB0 - bj1) * HEADS + h);
            bc[6] = __ldg(bias_table + (size_t)(CiB1 - bj0) * HEADS + h);
            bc[7] = __ldg(bias_table + (size_t)(CiB1 - bj1) * HEADS + h);
        }

        for (int nt = 0; nt < 37; nt++) {
            // S tiles with 2-way split accumulation chains (ILP)
            float cAx[4] = {0.f, 0.f, 0.f, 0.f}, cAy[4] = {0.f, 0.f, 0.f, 0.f};
            float cBx[4] = {0.f, 0.f, 0.f, 0.f}, cBy[4] = {0.f, 0.f, 0.f, 0.f};
#pragma unroll
            for (int kk = 0; kk < 2; kk++) {
                unsigned b[2];
                b[0] = fbits(Ks[(nt * 8 + g) * QS + kk * 8 + t]);
                b[1] = fbits(Ks[(nt * 8 + g) * QS + kk * 8 + t + 4]);
                mma_tf32(cAx, qaA[kk], b);
                mma_tf32(cBx, qaB[kk], b);
            }
#pragma unroll
            for (int kk = 2; kk < 4; kk++) {
                unsigned b[2];
                b[0] = fbits(Ks[(nt * 8 + g) * QS + kk * 8 + t]);
                b[1] = fbits(Ks[(nt * 8 + g) * QS + kk * 8 + t + 4]);
                mma_tf32(cAy, qaA[kk], b);
                mma_tf32(cBy, qaB[kk], b);
            }

            // prefetch NEXT iteration's bias (independent of the mma results)
            float bn[8];
            if (nt < 36) {
                int k0 = (nt + 1) * 8 + 2 * t, k1 = k0 + 1;
                int bj0 = bJ[k0], bj1 = bJ[k1];
                bn[0] = __ldg(bias_table + (size_t)(CiA0 - bj0) * HEADS + h);
                bn[1] = __ldg(bias_table + (size_t)(CiA0 - bj1) * HEADS + h);
                bn[2] = __ldg(bias_table + (size_t)(CiA1 - bj0) * HEADS + h);
                bn[3] = __ldg(bias_table + (size_t)(CiA1 - bj1) * HEADS + h);
                bn[4] = __ldg(bias_table + (size_t)(CiB0 - bj0) * HEADS + h);
                bn[5] = __ldg(bias_table + (size_t)(CiB0 - bj1) * HEADS + h);
                bn[6] = __ldg(bias_table + (size_t)(CiB1 - bj0) * HEADS + h);
                bn[7] = __ldg(bias_table + (size_t)(CiB1 - bj1) * HEADS + h);
            }

            const int j0 = nt * 8 + 2 * t, j1 = j0 + 1;
            const bool v0 = (j0 < NTOK), v1 = (j1 < NTOK);

            float pA0 = v0 ? __expf(cAx[0] + cAy[0] + bc[0]) : 0.f;
            float pA1 = v1 ? __expf(cAx[1] + cAy[1] + bc[1]) : 0.f;
            float pA2 = v0 ? __expf(cAx[2] + cAy[2] + bc[2]) : 0.f;
            float pA3 = v1 ? __expf(cAx[3] + cAy[3] + bc[3]) : 0.f;
            float pB0 = v0 ? __expf(cBx[0] + cBy[0] + bc[4]) : 0.f;
            float pB1 = v1 ? __expf(cBx[1] + cBy[1] + bc[5]) : 0.f;
            float pB2 = v0 ? __expf(cBx[2] + cBy[2] + bc[6]) : 0.f;
            float pB3 = v1 ? __expf(cBx[3] + cBy[3] + bc[7]) : 0.f;
            sA0 += pA0 + pA1;  sA1 += pA2 + pA3;
            sB0 += pB0 + pB1;  sB1 += pB2 + pB3;

            unsigned uA0 = f2tf(pA0), uA1 = f2tf(pA1), uA2 = f2tf(pA2), uA3 = f2tf(pA3);
            unsigned uB0 = f2tf(pB0), uB1 = f2tf(pB1), uB2 = f2tf(pB2), uB3 = f2tf(pB3);

            unsigned paA[4], paB[4];
            {
                unsigned a0 = __shfl_sync(0xffffffffu, uA0, src1);
                unsigned a1 = __shfl_sync(0xffffffffu, uA1, src1);
                unsigned a2 = __shfl_sync(0xffffffffu, uA2, src1);
                unsigned a3 = __shfl_sync(0xffffffffu, uA3, src1);
                unsigned b0 = __shfl_sync(0xffffffffu, uA0, src2);
                unsigned b1 = __shfl_sync(0xffffffffu, uA1, src2);
                unsigned b2 = __shfl_sync(0xffffffffu, uA2, src2);
                unsigned b3 = __shfl_sync(0xffffffffu, uA3, src2);
                paA[0] = (t & 1) ? a1 : a0;
                paA[1] = (t & 1) ? a3 : a2;
                paA[2] = (t & 1) ? b1 : b0;
                paA[3] = (t & 1) ? b3 : b2;
            }
            {
                unsigned a0 = __shfl_sync(0xffffffffu, uB0, src1);
                unsigned a1 = __shfl_sync(0xffffffffu, uB1, src1);
                unsigned a2 = __shfl_sync(0xffffffffu, uB2, src1);
                unsigned a3 = __shfl_sync(0xffffffffu, uB3, src1);
                unsigned b0 = __shfl_sync(0xffffffffu, uB0, src2);
                unsigned b1 = __shfl_sync(0xffffffffu, uB1, src2);
                unsigned b2 = __shfl_sync(0xffffffffu, uB2, src2);
                unsigned b3 = __shfl_sync(0xffffffffu, uB3, src2);
                paB[0] = (t & 1) ? a1 : a0;
                paB[1] = (t & 1) ? a3 : a2;
                paB[2] = (t & 1) ? b1 : b0;
                paB[3] = (t & 1) ? b3 : b2;
            }

#pragma unroll
            for (int ot = 0; ot < 4; ot++) {
                unsigned vb[2];
                vb[0] = fbits(Vs[(nt * 8 + t)     * VS + ot * 8 + g]);
                vb[1] = fbits(Vs[(nt * 8 + t + 4) * VS + ot * 8 + g]);
                mma_tf32(OA[ot], paA, vb);
                mma_tf32(OB[ot], paB, vb);
            }

#pragma unroll
            for (int i = 0; i < 8; i++) bc[i] = bn[i];
        }

        sA0 += __shfl_xor_sync(0xffffffffu, sA0, 1);
        sA0 += __shfl_xor_sync(0xffffffffu, sA0, 2);
        sA1 += __shfl_xor_sync(0xffffffffu, sA1, 1);
        sA1 += __shfl_xor_sync(0xffffffffu, sA1, 2);
        sB0 += __shfl_xor_sync(0xffffffffu, sB0, 1);
        sB0 += __shfl_xor_sync(0xffffffffu, sB0, 2);
        sB1 += __shfl_xor_sync(0xffffffffu, sB1, 1);
        sB1 += __shfl_xor_sync(0xffffffffu, sB1, 2);
        const float iA0 = 1.f / sA0, iA1 = 1.f / sA1;
        const float iB0 = 1.f / sB0, iB1 = 1.f / sB1;

        if (rA0 < NTOK) {
            float* d = g_ctx + ((size_t)w * NTOK + rA0) * D_MODEL + h * DH;
#pragma unroll
            for (int ot = 0; ot < 4; ot++)
                *(float2*)(d + ot * 8 + 2 * t) =
                    make_float2(__uint_as_float(f2tf(OA[ot][0] * iA0)),
                                __uint_as_float(f2tf(OA[ot][1] * iA0)));
        }
        if (rA1 < NTOK) {
            float* d = g_ctx + ((size_t)w * NTOK + rA1) * D_MODEL + h * DH;
#pragma unroll
            for (int ot = 0; ot < 4; ot++)
                *(float2*)(d + ot * 8 + 2 * t) =
                    make_float2(__uint_as_float(f2tf(OA[ot][2] * iA1)),
                                __uint_as_float(f2tf(OA[ot][3] * iA1)));
        }
        if (mtB != mtA) {
            if (rB0 < NTOK) {
                float* d = g_ctx + ((size_t)w * NTOK + rB0) * D_MODEL + h * DH;
#pragma unroll
                for (int ot = 0; ot < 4; ot++)
                    *(float2*)(d + ot * 8 + 2 * t) =
                        make_float2(__uint_as_float(f2tf(OB[ot][0] * iB0)),
                                    __uint_as_float(f2tf(OB[ot][1] * iB0)));
            }
            if (rB1 < NTOK) {
                float* d = g_ctx + ((size_t)w * NTOK + rB1) * D_MODEL + h * DH;
#pragma unroll
                for (int ot = 0; ot < 4; ot++)
                    *(float2*)(d + ot * 8 + 2 * t) =
                        make_float2(__uint_as_float(f2tf(OB[ot][2] * iB1)),
                                    __uint_as_float(f2tf(OB[ot][3] * iB1)));
            }
        }
    }
}

// ===========================================================================
// Kernel 3: output projection. cp.async double-buffer, zero cvts.
// ===========================================================================
__global__ __launch_bounds__(128) void out_gemm_tc(float* __restrict__ out)
{
    __shared__ float As[2][64 * QS];
    __shared__ float Bs[2][32 * BS2];
    __shared__ int   rowbase[64];

    const int tid  = threadIdx.x;
    const int lane = tid & 31, wid = tid >> 5;
    const int wm = wid & 1, wn = wid >> 1;
    const int g = lane >> 2, t = lane & 3;
    const int r0 = blockIdx.y * 64;      // row block (slow dim)
    const int c0 = blockIdx.x * 128;     // col block (fast dim)

    if (tid < 64) rowbase[tid] = x_offset(r0 + tid);
    __syncthreads();

    const float* asrc[4]; unsigned adst[4];
    const float* bsrc[8]; unsigned bdst[8];
#pragma unroll
    for (int i = 0; i < 4; i++) {
        int idx = tid + i * 128;
        int ar = idx >> 3, aq = idx & 7;
        asrc[i] = g_ctx + (size_t)(r0 + ar) * D_MODEL + aq * 4;
        adst[i] = (unsigned)__cvta_generic_to_shared(&As[0][ar * QS + aq * 4]);
    }
#pragma unroll
    for (int i = 0; i < 8; i++) {
        int idx = tid + i * 128;
        int bk = idx >> 5, bc = idx & 31;
        bsrc[i] = g_wout + bk * D_MODEL + c0 + bc * 4;
        bdst[i] = (unsigned)__cvta_generic_to_shared(&Bs[0][bk * BS2 + bc * 4]);
    }
    const unsigned ABYTES = 64 * QS * 4;
    const unsigned BBYTES = 32 * BS2 * 4;

    float acc[2][8][4];
#pragma unroll
    for (int m = 0; m < 2; m++)
#pragma unroll
        for (int n = 0; n < 8; n++)
#pragma unroll
            for (int e = 0; e < 4; e++) acc[m][n][e] = 0.f;

#pragma unroll
    for (int i = 0; i < 4; i++) cp16(adst[i], asrc[i]);
#pragma unroll
    for (int i = 0; i < 8; i++) cp16(bdst[i], bsrc[i]);
    cp_commit();

    for (int it = 0; it < 8; it++) {
        const int cur = it & 1;
        cp_wait0();
        __syncthreads();
        if (it < 7) {
            const int k0 = (it + 1) * 32;
            const unsigned nb = (it + 1) & 1;
#pragma unroll
            for (int i = 0; i < 4; i++) cp16(adst[i] + nb * ABYTES, asrc[i] + k0);
#pragma unroll
            for (int i = 0; i < 8; i++) cp16(bdst[i] + nb * BBYTES, bsrc[i] + (size_t)k0 * D_MODEL);
            cp_commit();
        }
#pragma unroll
        for (int kk = 0; kk < 4; kk++) {
            unsigned afr[2][4];
#pragma unroll
            for (int mt = 0; mt < 2; mt++) {
                int mr = wm * 32 + mt * 16;
                afr[mt][0] = fbits(As[cur][(mr + g)     * QS + kk * 8 + t]);
                afr[mt][1] = fbits(As[cur][(mr + g + 8) * QS + kk * 8 + t]);
                afr[mt][2] = fbits(As[cur][(mr + g)     * QS + kk * 8 + t + 4]);
                afr[mt][3] = fbits(As[cur][(mr + g + 8) * QS + kk * 8 + t + 4]);
            }
#pragma unroll
            for (int nt = 0; nt < 8; nt++) {
                int nc = wn * 64 + nt * 8;
                unsigned bfr[2];
                bfr[0] = fbits(Bs[cur][(kk * 8 + t)     * BS2 + nc + g]);
                bfr[1] = fbits(Bs[cur][(kk * 8 + t + 4) * BS2 + nc + g]);
                mma_tf32(acc[0][nt], afr[0], bfr);
                mma_tf32(acc[1][nt], afr[1], bfr);
            }
        }
    }

#pragma unroll
    for (int mt = 0; mt < 2; mt++) {
#pragma unroll
        for (int e = 0; e < 2; e++) {
            int rl = wm * 32 + mt * 16 + g + e * 8;
            int xb = rowbase[rl];
#pragma unroll
            for (int nt = 0; nt < 8; nt++) {
                int cc = c0 + wn * 64 + nt * 8 + 2 * t;
                *(float2*)(out + xb + cc) =
                    make_float2(acc[mt][nt][e * 2 + 0], acc[mt][nt][e * 2 + 1]);
            }
        }
    }
}

// ---------------------------------------------------------------------------
// Launch
// ---------------------------------------------------------------------------
extern "C" void kernel_launch(void* const* d_in, const int* in_sizes, int n_in,
                              void* d_out, int out_size)
{
    const float* x    = (const float*)d_in[0];
    const float* Wq   = (const float*)d_in[1];
    const float* bq   = (const float*)d_in[2];
    const float* Wkv  = (const float*)d_in[3];
    const float* bkv  = (const float*)d_in[4];
    const float* Wout = (const float*)d_in[5];
    const float* bias = (const float*)d_in[6];
    float* out = (float*)d_out;

    const int attn_smem = (NPAD * QS + NPAD * VS) * 4 + NPAD * 4;  // 93632 B
    cudaFuncSetAttribute(attn_flash,
                         cudaFuncAttributeMaxDynamicSharedMemorySize, attn_smem);

    conv_w<<<768, 256>>>(Wq, Wkv, Wout);

    dim3 g1(QKV_N / 128, M_ROWS / 64);    // (6, 1323) — cols fast
    qkv_gemm_tc<<<g1, 128>>>(x, bq, bkv);

    attn_flash<<<NWIN * HEADS, 320, attn_smem>>>(bias);

    dim3 g2(D_MODEL / 128, M_ROWS / 64);  // (2, 1323) — cols fast
    out_gemm_tc<<<g2, 128>>>(out);
}

// round 14
// speedup vs baseline: 1.3637x; 1.3637x over previous
#include <cuda_runtime.h>

// ---------------------------------------------------------------------------
// Problem constants
// ---------------------------------------------------------------------------
#define NTOK    294
#define NPAD    304            // padded tokens (19 * 16)
#define NT16    19
#define NWIN    288
#define D_MODEL 256
#define HEADS   8
#define DH      32
#define M_ROWS  (NWIN * NTOK)  // 84672
#define QKV_N   768

// smem strides (floats), conflict-free for the tf32 fragment access patterns
#define QS   36   // K rows (32 cols): banks 4g+t bijective
#define VS   40   // V rows (32 cols): banks 8t+g bijective
#define BS2  136  // GEMM B tile rows (128 cols): banks 8t+g bijective

// ---------------------------------------------------------------------------
// Scratch
// ---------------------------------------------------------------------------
__device__ float g_q   [(size_t)NWIN * HEADS * NTOK * DH];
__device__ float g_k   [(size_t)NWIN * HEADS * NTOK * DH];
__device__ float g_v   [(size_t)NWIN * HEADS * NTOK * DH];
__device__ float g_ctx [(size_t)M_ROWS * D_MODEL];
__device__ float g_wqkv[256 * 768];   // [k][n], tf32 bits
__device__ float g_wout[256 * 256];   // [k][n], tf32 bits

__device__ __forceinline__ int x_offset(int r) {
    int w  = r / NTOK;  int t   = r - w * NTOK;
    int bb = w / 144;   int rem = w - bb * 144;
    int gx = rem / 12;  int gy  = rem - gx * 12;
    int l  = t / 49;    int t2  = t - l * 49;
    int w1 = t2 / 7;    int w2  = t2 - w1 * 7;
    return (((((bb * 6 + l) * 12 + gx) * 12 + gy) * 7 + w1) * 7 + w2) * D_MODEL;
}

__device__ __forceinline__ unsigned f2tf(float f) {
    unsigned u;
    asm("cvt.rna.tf32.f32 %0, %1;" : "=r"(u) : "f"(f));
    return u;
}
__device__ __forceinline__ unsigned fbits(float f) { return __float_as_uint(f); }

__device__ __forceinline__ void mma_tf32(float c[4], const unsigned a[4], const unsigned b[2]) {
    asm volatile(
        "mma.sync.aligned.m16n8k8.row.col.f32.tf32.tf32.f32 "
        "{%0,%1,%2,%3}, {%4,%5,%6,%7}, {%8,%9}, {%0,%1,%2,%3};"
        : "+f"(c[0]), "+f"(c[1]), "+f"(c[2]), "+f"(c[3])
        : "r"(a[0]), "r"(a[1]), "r"(a[2]), "r"(a[3]), "r"(b[0]), "r"(b[1]));
}

__device__ __forceinline__ void cp16(unsigned dst, const void* src) {
    asm volatile("cp.async.cg.shared.global [%0], [%1], 16;" :: "r"(dst), "l"(src));
}
__device__ __forceinline__ void cp_commit() {
    asm volatile("cp.async.commit_group;" ::);
}
__device__ __forceinline__ void cp_wait0() {
    asm volatile("cp.async.wait_group 0;" ::: "memory");
}

// ===========================================================================
// Kernel 0: one-time weight conversion to tf32 ([k][n] layouts).
// ===========================================================================
__global__ __launch_bounds__(256) void conv_w(
    const float* __restrict__ Wq, const float* __restrict__ Wkv,
    const float* __restrict__ Wout)
{
    int idx = blockIdx.x * 256 + threadIdx.x;
    if (idx < 256 * 768) {
        int k = idx / 768, n = idx - k * 768;
        float v = (n < 256) ? Wq[k * 256 + n] : Wkv[k * 512 + (n - 256)];
        g_wqkv[idx] = __uint_as_float(f2tf(v));
    }
    if (idx < 256 * 256) {
        g_wout[idx] = __uint_as_float(f2tf(Wout[idx]));
    }
}

// ===========================================================================
// Kernel 1: QKV projection. CTA 64x128, 4 warps of 32x64, BK=32.
// cp.async double-buffer; x staged RAW (HMMA truncates); weights pre-rounded.
// ===========================================================================
__global__ __launch_bounds__(128) void qkv_gemm_tc(
    const float* __restrict__ x,
    const float* __restrict__ bq, const float* __restrict__ bkv)
{
    __shared__ float As[2][64 * QS];
    __shared__ float Bs[2][32 * BS2];
    __shared__ int   rowbase[64];

    const int tid  = threadIdx.x;
    const int lane = tid & 31, wid = tid >> 5;
    const int wm = wid & 1, wn = wid >> 1;
    const int g = lane >> 2, t = lane & 3;
    const int r0 = blockIdx.y * 64;      // row block (slow dim)
    const int c0 = blockIdx.x * 128;     // col block (fast dim)

    if (tid < 64) rowbase[tid] = x_offset(r0 + tid);
    __syncthreads();

    const float* asrc[4]; unsigned adst[4];
    const float* bsrc[8]; unsigned bdst[8];
#pragma unroll
    for (int i = 0; i < 4; i++) {
        int idx = tid + i * 128;
        int ar = idx >> 3, aq = idx & 7;
        asrc[i] = x + rowbase[ar] + aq * 4;
        adst[i] = (unsigned)__cvta_generic_to_shared(&As[0][ar * QS + aq * 4]);
    }
#pragma unroll
    for (int i = 0; i < 8; i++) {
        int idx = tid + i * 128;
        int bk = idx >> 5, bc = idx & 31;
        bsrc[i] = g_wqkv + bk * QKV_N + c0 + bc * 4;
        bdst[i] = (unsigned)__cvta_generic_to_shared(&Bs[0][bk * BS2 + bc * 4]);
    }
    const unsigned ABYTES = 64 * QS * 4;
    const unsigned BBYTES = 32 * BS2 * 4;

    float acc[2][8][4];
#pragma unroll
    for (int m = 0; m < 2; m++)
#pragma unroll
        for (int n = 0; n < 8; n++)
#pragma unroll
            for (int e = 0; e < 4; e++) acc[m][n][e] = 0.f;

#pragma unroll
    for (int i = 0; i < 4; i++) cp16(adst[i], asrc[i]);
#pragma unroll
    for (int i = 0; i < 8; i++) cp16(bdst[i], bsrc[i]);
    cp_commit();

    for (int it = 0; it < 8; it++) {
        const int cur = it & 1;
        cp_wait0();
        __syncthreads();
        if (it < 7) {
            const int k0 = (it + 1) * 32;
            const unsigned nb = (it + 1) & 1;
#pragma unroll
            for (int i = 0; i < 4; i++) cp16(adst[i] + nb * ABYTES, asrc[i] + k0);
#pragma unroll
            for (int i = 0; i < 8; i++) cp16(bdst[i] + nb * BBYTES, bsrc[i] + (size_t)k0 * QKV_N);
            cp_commit();
        }
#pragma unroll
        for (int kk = 0; kk < 4; kk++) {
            unsigned afr[2][4];
#pragma unroll
            for (int mt = 0; mt < 2; mt++) {
                int mr = wm * 32 + mt * 16;
                afr[mt][0] = fbits(As[cur][(mr + g)     * QS + kk * 8 + t]);
                afr[mt][1] = fbits(As[cur][(mr + g + 8) * QS + kk * 8 + t]);
                afr[mt][2] = fbits(As[cur][(mr + g)     * QS + kk * 8 + t + 4]);
                afr[mt][3] = fbits(As[cur][(mr + g + 8) * QS + kk * 8 + t + 4]);
            }
#pragma unroll
            for (int nt = 0; nt < 8; nt++) {
                int nc = wn * 64 + nt * 8;
                unsigned bfr[2];
                bfr[0] = fbits(Bs[cur][(kk * 8 + t)     * BS2 + nc + g]);
                bfr[1] = fbits(Bs[cur][(kk * 8 + t + 4) * BS2 + nc + g]);
                mma_tf32(acc[0][nt], afr[0], bfr);
                mma_tf32(acc[1][nt], afr[1], bfr);
            }
        }
    }

    const float scale = 0.17677669529663687f;
#pragma unroll
    for (int mt = 0; mt < 2; mt++) {
#pragma unroll
        for (int e = 0; e < 2; e++) {
            int r = r0 + wm * 32 + mt * 16 + g + e * 8;
            int w = r / NTOK;  int tok = r - w * NTOK;
#pragma unroll
            for (int nt = 0; nt < 8; nt++) {
                int nc = c0 + wn * 64 + nt * 8 + 2 * t;     // even; pair {nc, nc+1}
                float va0 = acc[mt][nt][e * 2 + 0];
                float va1 = acc[mt][nt][e * 2 + 1];
                if (nc < D_MODEL) {
                    int h = nc >> 5, c = nc & 31;
                    float2 v2 = make_float2(
                        __uint_as_float(f2tf((va0 + __ldg(bq + nc))     * scale)),
                        __uint_as_float(f2tf((va1 + __ldg(bq + nc + 1)) * scale)));
                    *(float2*)(g_q + (((size_t)w * HEADS + h) * NTOK + tok) * DH + c) = v2;
                } else {
                    int kc = nc - D_MODEL;
                    float2 v2 = make_float2(
                        __uint_as_float(f2tf(va0 + __ldg(bkv + kc))),
                        __uint_as_float(f2tf(va1 + __ldg(bkv + kc + 1))));
                    if (kc < D_MODEL) {
                        int h = kc >> 5, c = kc & 31;
                        *(float2*)(g_k + (((size_t)w * HEADS + h) * NTOK + tok) * DH + c) = v2;
                    } else {
                        int vc = kc - D_MODEL;
                        int h = vc >> 5, c = vc & 31;
                        *(float2*)(g_v + (((size_t)w * HEADS + h) * NTOK + tok) * DH + c) = v2;
                    }
                }
            }
        }
    }
}

// ===========================================================================
// Kernel 2: register-resident flash attention — EXACT R12 configuration
// (256 threads / 8 warps / 2 CTAs/SM => 128-reg budget, no spills).
// TWO 16-row query tiles per warp sharing every K/V fragment load.
// ===========================================================================
__global__ __launch_bounds__(256, 2) void attn_flash(const float* __restrict__ bias_table)
{
    extern __shared__ float sm[];
    float* Ks = sm;                       // NPAD x 36
    float* Vs = sm + NPAD * QS;           // NPAD x 40
    int*   bJ = (int*)(Vs + NPAD * VS);   // NPAD

    const int wh = blockIdx.x;
    const int w  = wh >> 3, h = wh & 7;
    const int tid = threadIdx.x;
    const int lane = tid & 31, wid = tid >> 5;
    const int g = lane >> 2, t = lane & 3;

    const float* kg = g_k + (size_t)wh * NTOK * DH;
    const float* vg = g_v + (size_t)wh * NTOK * DH;
    for (int idx = tid; idx < NTOK * 8; idx += 256) {
        int row = idx >> 3, q4 = (idx & 7) * 4;
        *(float4*)(Ks + row * QS + q4) = *(const float4*)(kg + row * DH + q4);
        *(float4*)(Vs + row * VS + q4) = *(const float4*)(vg + row * DH + q4);
    }
    for (int idx = tid; idx < (NPAD - NTOK) * 8; idx += 256) {
        int row = NTOK + (idx >> 3), q4 = (idx & 7) * 4;
        float4 z = make_float4(0.f, 0.f, 0.f, 0.f);
        *(float4*)(Ks + row * QS + q4) = z;
        *(float4*)(Vs + row * VS + q4) = z;
    }
    for (int j = tid; j < NPAD; j += 256) {
        int jj = min(j, NTOK - 1);
        int l = jj / 49, r2 = jj - l * 49, a = r2 / 7, b = r2 - a * 7;
        bJ[j] = l * 169 + a * 13 + b;
    }
    __syncthreads();

    const float* qg = g_q + (size_t)wh * NTOK * DH;

    // 10 tile-pairs over 8 warps: pair p covers tiles (2p, min(2p+1,18))
    for (int p = wid; p < 10; p += 8) {
        const int mtA = 2 * p;
        const int mtB = min(2 * p + 1, NT16 - 1);

        const int rA0 = mtA * 16 + g, rA1 = rA0 + 8;
        const int rB0 = mtB * 16 + g, rB1 = rB0 + 8;
        const int cA0 = min(rA0, NTOK - 1), cA1 = min(rA1, NTOK - 1);
        const int cB0 = min(rB0, NTOK - 1), cB1 = min(rB1, NTOK - 1);

        int CiA0, CiA1, CiB0, CiB1;
        {
            int l, r2, a, b;
            l = cA0 / 49; r2 = cA0 - l * 49; a = r2 / 7; b = r2 - a * 7;
            CiA0 = (l + 5) * 169 + (a + 6) * 13 + (b + 6);
            l = cA1 / 49; r2 = cA1 - l * 49; a = r2 / 7; b = r2 - a * 7;
            CiA1 = (l + 5) * 169 + (a + 6) * 13 + (b + 6);
            l = cB0 / 49; r2 = cB0 - l * 49; a = r2 / 7; b = r2 - a * 7;
            CiB0 = (l + 5) * 169 + (a + 6) * 13 + (b + 6);
            l = cB1 / 49; r2 = cB1 - l * 49; a = r2 / 7; b = r2 - a * 7;
            CiB1 = (l + 5) * 169 + (a + 6) * 13 + (b + 6);
        }

        unsigned qaA[4][4], qaB[4][4];
#pragma unroll
        for (int kk = 0; kk < 4; kk++) {
            qaA[kk][0] = fbits(__ldg(qg + cA0 * DH + kk * 8 + t));
            qaA[kk][1] = fbits(__ldg(qg + cA1 * DH + kk * 8 + t));
            qaA[kk][2] = fbits(__ldg(qg + cA0 * DH + kk * 8 + t + 4));
            qaA[kk][3] = fbits(__ldg(qg + cA1 * DH + kk * 8 + t + 4));
            qaB[kk][0] = fbits(__ldg(qg + cB0 * DH + kk * 8 + t));
            qaB[kk][1] = fbits(__ldg(qg + cB1 * DH + kk * 8 + t));
            qaB[kk][2] = fbits(__ldg(qg + cB0 * DH + kk * 8 + t + 4));
            qaB[kk][3] = fbits(__ldg(qg + cB1 * DH + kk * 8 + t + 4));
        }

        float OA[4][4], OB[4][4];
#pragma unroll
        for (int ot = 0; ot < 4; ot++)
#pragma unroll
            for (int e = 0; e < 4; e++) { OA[ot][e] = 0.f; OB[ot][e] = 0.f; }
        float sA0 = 0.f, sA1 = 0.f, sB0 = 0.f, sB1 = 0.f;

        const int src1 = (lane & 28) | (t >> 1);
        const int src2 = src1 + 2;

        for (int nt = 0; nt < 37; nt++) {
            // Two independent 2-chains per tile (ILP), combined at the end.
            float cAx[4] = {0.f, 0.f, 0.f, 0.f}, cAy[4] = {0.f, 0.f, 0.f, 0.f};
            float cBx[4] = {0.f, 0.f, 0.f, 0.f}, cBy[4] = {0.f, 0.f, 0.f, 0.f};
#pragma unroll
            for (int kk = 0; kk < 2; kk++) {
                unsigned b[2];
                b[0] = fbits(Ks[(nt * 8 + g) * QS + kk * 8 + t]);
                b[1] = fbits(Ks[(nt * 8 + g) * QS + kk * 8 + t + 4]);
                mma_tf32(cAx, qaA[kk], b);
                mma_tf32(cBx, qaB[kk], b);
            }
#pragma unroll
            for (int kk = 2; kk < 4; kk++) {
                unsigned b[2];
                b[0] = fbits(Ks[(nt * 8 + g) * QS + kk * 8 + t]);
                b[1] = fbits(Ks[(nt * 8 + g) * QS + kk * 8 + t + 4]);
                mma_tf32(cAy, qaA[kk], b);
                mma_tf32(cBy, qaB[kk], b);
            }
            float cA[4], cB[4];
#pragma unroll
            for (int e = 0; e < 4; e++) { cA[e] = cAx[e] + cAy[e]; cB[e] = cBx[e] + cBy[e]; }

            const int j0 = nt * 8 + 2 * t, j1 = j0 + 1;
            const int bj0 = bJ[j0], bj1 = bJ[j1];
            const bool v0 = (j0 < NTOK), v1 = (j1 < NTOK);

            float pA0 = v0 ? __expf(cA[0] + __ldg(bias_table + (size_t)(CiA0 - bj0) * HEADS + h)) : 0.f;
            float pA1 = v1 ? __expf(cA[1] + __ldg(bias_table + (size_t)(CiA0 - bj1) * HEADS + h)) : 0.f;
            float pA2 = v0 ? __expf(cA[2] + __ldg(bias_table + (size_t)(CiA1 - bj0) * HEADS + h)) : 0.f;
            float pA3 = v1 ? __expf(cA[3] + __ldg(bias_table + (size_t)(CiA1 - bj1) * HEADS + h)) : 0.f;
            float pB0 = v0 ? __expf(cB[0] + __ldg(bias_table + (size_t)(CiB0 - bj0) * HEADS + h)) : 0.f;
            float pB1 = v1 ? __expf(cB[1] + __ldg(bias_table + (size_t)(CiB0 - bj1) * HEADS + h)) : 0.f;
            float pB2 = v0 ? __expf(cB[2] + __ldg(bias_table + (size_t)(CiB1 - bj0) * HEADS + h)) : 0.f;
            float pB3 = v1 ? __expf(cB[3] + __ldg(bias_table + (size_t)(CiB1 - bj1) * HEADS + h)) : 0.f;
            sA0 += pA0 + pA1;  sA1 += pA2 + pA3;
            sB0 += pB0 + pB1;  sB1 += pB2 + pB3;

            unsigned uA0 = f2tf(pA0), uA1 = f2tf(pA1), uA2 = f2tf(pA2), uA3 = f2tf(pA3);
            unsigned uB0 = f2tf(pB0), uB1 = f2tf(pB1), uB2 = f2tf(pB2), uB3 = f2tf(pB3);

            unsigned paA[4], paB[4];
            {
                unsigned a0 = __shfl_sync(0xffffffffu, uA0, src1);
                unsigned a1 = __shfl_sync(0xffffffffu, uA1, src1);
                unsigned a2 = __shfl_sync(0xffffffffu, uA2, src1);
                unsigned a3 = __shfl_sync(0xffffffffu, uA3, src1);
                unsigned b0 = __shfl_sync(0xffffffffu, uA0, src2);
                unsigned b1 = __shfl_sync(0xffffffffu, uA1, src2);
                unsigned b2 = __shfl_sync(0xffffffffu, uA2, src2);
                unsigned b3 = __shfl_sync(0xffffffffu, uA3, src2);
                paA[0] = (t & 1) ? a1 : a0;
                paA[1] = (t & 1) ? a3 : a2;
                paA[2] = (t & 1) ? b1 : b0;
                paA[3] = (t & 1) ? b3 : b2;
            }
            {
                unsigned a0 = __shfl_sync(0xffffffffu, uB0, src1);
                unsigned a1 = __shfl_sync(0xffffffffu, uB1, src1);
                unsigned a2 = __shfl_sync(0xffffffffu, uB2, src1);
                unsigned a3 = __shfl_sync(0xffffffffu, uB3, src1);
                unsigned b0 = __shfl_sync(0xffffffffu, uB0, src2);
                unsigned b1 = __shfl_sync(0xffffffffu, uB1, src2);
                unsigned b2 = __shfl_sync(0xffffffffu, uB2, src2);
                unsigned b3 = __shfl_sync(0xffffffffu, uB3, src2);
                paB[0] = (t & 1) ? a1 : a0;
                paB[1] = (t & 1) ? a3 : a2;
                paB[2] = (t & 1) ? b1 : b0;
                paB[3] = (t & 1) ? b3 : b2;
            }

#pragma unroll
            for (int ot = 0; ot < 4; ot++) {
                unsigned vb[2];
                vb[0] = fbits(Vs[(nt * 8 + t)     * VS + ot * 8 + g]);
                vb[1] = fbits(Vs[(nt * 8 + t + 4) * VS + ot * 8 + g]);
                mma_tf32(OA[ot], paA, vb);
                mma_tf32(OB[ot], paB, vb);
            }
        }

        sA0 += __shfl_xor_sync(0xffffffffu, sA0, 1);
        sA0 += __shfl_xor_sync(0xffffffffu, sA0, 2);
        sA1 += __shfl_xor_sync(0xffffffffu, sA1, 1);
        sA1 += __shfl_xor_sync(0xffffffffu, sA1, 2);
        sB0 += __shfl_xor_sync(0xffffffffu, sB0, 1);
        sB0 += __shfl_xor_sync(0xffffffffu, sB0, 2);
        sB1 += __shfl_xor_sync(0xffffffffu, sB1, 1);
        sB1 += __shfl_xor_sync(0xffffffffu, sB1, 2);
        const float iA0 = 1.f / sA0, iA1 = 1.f / sA1;
        const float iB0 = 1.f / sB0, iB1 = 1.f / sB1;

        if (rA0 < NTOK) {
            float* d = g_ctx + ((size_t)w * NTOK + rA0) * D_MODEL + h * DH;
#pragma unroll
            for (int ot = 0; ot < 4; ot++)
                *(float2*)(d + ot * 8 + 2 * t) =
                    make_float2(__uint_as_float(f2tf(OA[ot][0] * iA0)),
                                __uint_as_float(f2tf(OA[ot][1] * iA0)));
        }
        if (rA1 < NTOK) {
            float* d = g_ctx + ((size_t)w * NTOK + rA1) * D_MODEL + h * DH;
#pragma unroll
            for (int ot = 0; ot < 4; ot++)
                *(float2*)(d + ot * 8 + 2 * t) =
                    make_float2(__uint_as_float(f2tf(OA[ot][2] * iA1)),
                                __uint_as_float(f2tf(OA[ot][3] * iA1)));
        }
        if (mtB != mtA) {
            if (rB0 < NTOK) {
                float* d = g_ctx + ((size_t)w * NTOK + rB0) * D_MODEL + h * DH;
#pragma unroll
                for (int ot = 0; ot < 4; ot++)
                    *(float2*)(d + ot * 8 + 2 * t) =
                        make_float2(__uint_as_float(f2tf(OB[ot][0] * iB0)),
                                    __uint_as_float(f2tf(OB[ot][1] * iB0)));
            }
            if (rB1 < NTOK) {
                float* d = g_ctx + ((size_t)w * NTOK + rB1) * D_MODEL + h * DH;
#pragma unroll
                for (int ot = 0; ot < 4; ot++)
                    *(float2*)(d + ot * 8 + 2 * t) =
                        make_float2(__uint_as_float(f2tf(OB[ot][2] * iB1)),
                                    __uint_as_float(f2tf(OB[ot][3] * iB1)));
            }
        }
    }
}

// ===========================================================================
// Kernel 3: output projection. cp.async double-buffer, zero cvts.
// ===========================================================================
__global__ __launch_bounds__(128) void out_gemm_tc(float* __restrict__ out)
{
    __shared__ float As[2][64 * QS];
    __shared__ float Bs[2][32 * BS2];
    __shared__ int   rowbase[64];

    const int tid  = threadIdx.x;
    const int lane = tid & 31, wid = tid >> 5;
    const int wm = wid & 1, wn = wid >> 1;
    const int g = lane >> 2, t = lane & 3;
    const int r0 = blockIdx.y * 64;      // row block (slow dim)
    const int c0 = blockIdx.x * 128;     // col block (fast dim)

    if (tid < 64) rowbase[tid] = x_offset(r0 + tid);
    __syncthreads();

    const float* asrc[4]; unsigned adst[4];
    const float* bsrc[8]; unsigned bdst[8];
#pragma unroll
    for (int i = 0; i < 4; i++) {
        int idx = tid + i * 128;
        int ar = idx >> 3, aq = idx & 7;
        asrc[i] = g_ctx + (size_t)(r0 + ar) * D_MODEL + aq * 4;
        adst[i] = (unsigned)__cvta_generic_to_shared(&As[0][ar * QS + aq * 4]);
    }
#pragma unroll
    for (int i = 0; i < 8; i++) {
        int idx = tid + i * 128;
        int bk = idx >> 5, bc = idx & 31;
        bsrc[i] = g_wout + bk * D_MODEL + c0 + bc * 4;
        bdst[i] = (unsigned)__cvta_generic_to_shared(&Bs[0][bk * BS2 + bc * 4]);
    }
    const unsigned ABYTES = 64 * QS * 4;
    const unsigned BBYTES = 32 * BS2 * 4;

    float acc[2][8][4];
#pragma unroll
    for (int m = 0; m < 2; m++)
#pragma unroll
        for (int n = 0; n < 8; n++)
#pragma unroll
            for (int e = 0; e < 4; e++) acc[m][n][e] = 0.f;

#pragma unroll
    for (int i = 0; i < 4; i++) cp16(adst[i], asrc[i]);
#pragma unroll
    for (int i = 0; i < 8; i++) cp16(bdst[i], bsrc[i]);
    cp_commit();

    for (int it = 0; it < 8; it++) {
        const int cur = it & 1;
        cp_wait0();
        __syncthreads();
        if (it < 7) {
            const int k0 = (it + 1) * 32;
            const unsigned nb = (it + 1) & 1;
#pragma unroll
            for (int i = 0; i < 4; i++) cp16(adst[i] + nb * ABYTES, asrc[i] + k0);
#pragma unroll
            for (int i = 0; i < 8; i++) cp16(bdst[i] + nb * BBYTES, bsrc[i] + (size_t)k0 * D_MODEL);
            cp_commit();
        }
#pragma unroll
        for (int kk = 0; kk < 4; kk++) {
            unsigned afr[2][4];
#pragma unroll
            for (int mt = 0; mt < 2; mt++) {
                int mr = wm * 32 + mt * 16;
                afr[mt][0] = fbits(As[cur][(mr + g)     * QS + kk * 8 + t]);
                afr[mt][1] = fbits(As[cur][(mr + g + 8) * QS + kk * 8 + t]);
                afr[mt][2] = fbits(As[cur][(mr + g)     * QS + kk * 8 + t + 4]);
                afr[mt][3] = fbits(As[cur][(mr + g + 8) * QS + kk * 8 + t + 4]);
            }
#pragma unroll
            for (int nt = 0; nt < 8; nt++) {
                int nc = wn * 64 + nt * 8;
                unsigned bfr[2];
                bfr[0] = fbits(Bs[cur][(kk * 8 + t)     * BS2 + nc + g]);
                bfr[1] = fbits(Bs[cur][(kk * 8 + t + 4) * BS2 + nc + g]);
                mma_tf32(acc[0][nt], afr[0], bfr);
                mma_tf32(acc[1][nt], afr[1], bfr);
            }
        }
    }

#pragma unroll
    for (int mt = 0; mt < 2; mt++) {
#pragma unroll
        for (int e = 0; e < 2; e++) {
            int rl = wm * 32 + mt * 16 + g + e * 8;
            int xb = rowbase[rl];
#pragma unroll
            for (int nt = 0; nt < 8; nt++) {
                int cc = c0 + wn * 64 + nt * 8 + 2 * t;
                *(float2*)(out + xb + cc) =
                    make_float2(acc[mt][nt][e * 2 + 0], acc[mt][nt][e * 2 + 1]);
            }
        }
    }
}

// ---------------------------------------------------------------------------
// Launch
// ---------------------------------------------------------------------------
extern "C" void kernel_launch(void* const* d_in, const int* in_sizes, int n_in,
                              void* d_out, int out_size)
{
    const float* x    = (const float*)d_in[0];
    const float* Wq   = (const float*)d_in[1];
    const float* bq   = (const float*)d_in[2];
    const float* Wkv  = (const float*)d_in[3];
    const float* bkv  = (const float*)d_in[4];
    const float* Wout = (const float*)d_in[5];
    const float* bias = (const float*)d_in[6];
    float* out = (float*)d_out;

    const int attn_smem = (NPAD * QS + NPAD * VS) * 4 + NPAD * 4;  // 93632 B
    cudaFuncSetAttribute(attn_flash,
                         cudaFuncAttributeMaxDynamicSharedMemorySize, attn_smem);

    conv_w<<<768, 256>>>(Wq, Wkv, Wout);

    dim3 g1(QKV_N / 128, M_ROWS / 64);    // (6, 1323) — cols fast
    qkv_gemm_tc<<<g1, 128>>>(x, bq, bkv);

    attn_flash<<<NWIN * HEADS, 256, attn_smem>>>(bias);

    dim3 g2(D_MODEL / 128, M_ROWS / 64);  // (2, 1323) — cols fast
    out_gemm_tc<<<g2, 128>>>(out);
}

// round 15
// speedup vs baseline: 1.6013x; 1.1742x over previous
#include <cuda_runtime.h>

// ---------------------------------------------------------------------------
// Problem constants
// ---------------------------------------------------------------------------
#define NTOK    294
#define NPAD    304            // padded tokens (19 * 16)
#define NT16    19
#define NWIN    288
#define D_MODEL 256
#define HEADS   8
#define DH      32
#define M_ROWS  (NWIN * NTOK)  // 84672
#define QKV_N   768
#define NBIAS   1859           // (2*6-1)*(2*7-1)*(2*7-1)

// smem strides (floats), conflict-free for the tf32 fragment access patterns
#define QS   36   // K rows (32 cols): banks 4g+t bijective
#define VS   40   // V rows (32 cols): banks 8t+g bijective
#define BS2  136  // GEMM B tile rows (128 cols): banks 8t+g bijective

// ---------------------------------------------------------------------------
// Scratch
// ---------------------------------------------------------------------------
__device__ float g_q   [(size_t)NWIN * HEADS * NTOK * DH];
__device__ float g_k   [(size_t)NWIN * HEADS * NTOK * DH];
__device__ float g_v   [(size_t)NWIN * HEADS * NTOK * DH];
__device__ float g_ctx [(size_t)M_ROWS * D_MODEL];
__device__ float g_wqkv[256 * 768];   // [k][n], tf32 bits
__device__ float g_wout[256 * 256];   // [k][n], tf32 bits

__device__ __forceinline__ int x_offset(int r) {
    int w  = r / NTOK;  int t   = r - w * NTOK;
    int bb = w / 144;   int rem = w - bb * 144;
    int gx = rem / 12;  int gy  = rem - gx * 12;
    int l  = t / 49;    int t2  = t - l * 49;
    int w1 = t2 / 7;    int w2  = t2 - w1 * 7;
    return (((((bb * 6 + l) * 12 + gx) * 12 + gy) * 7 + w1) * 7 + w2) * D_MODEL;
}

__device__ __forceinline__ unsigned f2tf(float f) {
    unsigned u;
    asm("cvt.rna.tf32.f32 %0, %1;" : "=r"(u) : "f"(f));
    return u;
}
__device__ __forceinline__ unsigned fbits(float f) { return __float_as_uint(f); }

__device__ __forceinline__ void mma_tf32(float c[4], const unsigned a[4], const unsigned b[2]) {
    asm volatile(
        "mma.sync.aligned.m16n8k8.row.col.f32.tf32.tf32.f32 "
        "{%0,%1,%2,%3}, {%4,%5,%6,%7}, {%8,%9}, {%0,%1,%2,%3};"
        : "+f"(c[0]), "+f"(c[1]), "+f"(c[2]), "+f"(c[3])
        : "r"(a[0]), "r"(a[1]), "r"(a[2]), "r"(a[3]), "r"(b[0]), "r"(b[1]));
}

__device__ __forceinline__ void cp16(unsigned dst, const void* src) {
    asm volatile("cp.async.cg.shared.global [%0], [%1], 16;" :: "r"(dst), "l"(src));
}
__device__ __forceinline__ void cp_commit() {
    asm volatile("cp.async.commit_group;" ::);
}
__device__ __forceinline__ void cp_wait0() {
    asm volatile("cp.async.wait_group 0;" ::: "memory");
}

// ===========================================================================
// Kernel 0: one-time weight conversion to tf32 ([k][n] layouts).
// ===========================================================================
__global__ __launch_bounds__(256) void conv_w(
    const float* __restrict__ Wq, const float* __restrict__ Wkv,
    const float* __restrict__ Wout)
{
    int idx = blockIdx.x * 256 + threadIdx.x;
    if (idx < 256 * 768) {
        int k = idx / 768, n = idx - k * 768;
        float v = (n < 256) ? Wq[k * 256 + n] : Wkv[k * 512 + (n - 256)];
        g_wqkv[idx] = __uint_as_float(f2tf(v));
    }
    if (idx < 256 * 256) {
        g_wout[idx] = __uint_as_float(f2tf(Wout[idx]));
    }
}

// ===========================================================================
// Kernel 1: QKV projection. CTA 64x128, 4 warps of 32x64, BK=32.
// cp.async double-buffer; x staged RAW (HMMA truncates); weights pre-rounded.
// ===========================================================================
__global__ __launch_bounds__(128) void qkv_gemm_tc(
    const float* __restrict__ x,
    const float* __restrict__ bq, const float* __restrict__ bkv)
{
    __shared__ float As[2][64 * QS];
    __shared__ float Bs[2][32 * BS2];
    __shared__ int   rowbase[64];

    const int tid  = threadIdx.x;
    const int lane = tid & 31, wid = tid >> 5;
    const int wm = wid & 1, wn = wid >> 1;
    const int g = lane >> 2, t = lane & 3;
    const int r0 = blockIdx.y * 64;      // row block (slow dim)
    const int c0 = blockIdx.x * 128;     // col block (fast dim)

    if (tid < 64) rowbase[tid] = x_offset(r0 + tid);
    __syncthreads();

    const float* asrc[4]; unsigned adst[4];
    const float* bsrc[8]; unsigned bdst[8];
#pragma unroll
    for (int i = 0; i < 4; i++) {
        int idx = tid + i * 128;
        int ar = idx >> 3, aq = idx & 7;
        asrc[i] = x + rowbase[ar] + aq * 4;
        adst[i] = (unsigned)__cvta_generic_to_shared(&As[0][ar * QS + aq * 4]);
    }
#pragma unroll
    for (int i = 0; i < 8; i++) {
        int idx = tid + i * 128;
        int bk = idx >> 5, bc = idx & 31;
        bsrc[i] = g_wqkv + bk * QKV_N + c0 + bc * 4;
        bdst[i] = (unsigned)__cvta_generic_to_shared(&Bs[0][bk * BS2 + bc * 4]);
    }
    const unsigned ABYTES = 64 * QS * 4;
    const unsigned BBYTES = 32 * BS2 * 4;

    float acc[2][8][4];
#pragma unroll
    for (int m = 0; m < 2; m++)
#pragma unroll
        for (int n = 0; n < 8; n++)
#pragma unroll
            for (int e = 0; e < 4; e++) acc[m][n][e] = 0.f;

#pragma unroll
    for (int i = 0; i < 4; i++) cp16(adst[i], asrc[i]);
#pragma unroll
    for (int i = 0; i < 8; i++) cp16(bdst[i], bsrc[i]);
    cp_commit();

    for (int it = 0; it < 8; it++) {
        const int cur = it & 1;
        cp_wait0();
        __syncthreads();
        if (it < 7) {
            const int k0 = (it + 1) * 32;
            const unsigned nb = (it + 1) & 1;
#pragma unroll
            for (int i = 0; i < 4; i++) cp16(adst[i] + nb * ABYTES, asrc[i] + k0);
#pragma unroll
            for (int i = 0; i < 8; i++) cp16(bdst[i] + nb * BBYTES, bsrc[i] + (size_t)k0 * QKV_N);
            cp_commit();
        }
#pragma unroll
        for (int kk = 0; kk < 4; kk++) {
            unsigned afr[2][4];
#pragma unroll
            for (int mt = 0; mt < 2; mt++) {
                int mr = wm * 32 + mt * 16;
                afr[mt][0] = fbits(As[cur][(mr + g)     * QS + kk * 8 + t]);
                afr[mt][1] = fbits(As[cur][(mr + g + 8) * QS + kk * 8 + t]);
                afr[mt][2] = fbits(As[cur][(mr + g)     * QS + kk * 8 + t + 4]);
                afr[mt][3] = fbits(As[cur][(mr + g + 8) * QS + kk * 8 + t + 4]);
            }
#pragma unroll
            for (int nt = 0; nt < 8; nt++) {
                int nc = wn * 64 + nt * 8;
                unsigned bfr[2];
                bfr[0] = fbits(Bs[cur][(kk * 8 + t)     * BS2 + nc + g]);
                bfr[1] = fbits(Bs[cur][(kk * 8 + t + 4) * BS2 + nc + g]);
                mma_tf32(acc[0][nt], afr[0], bfr);
                mma_tf32(acc[1][nt], afr[1], bfr);
            }
        }
    }

    const float scale = 0.17677669529663687f;
#pragma unroll
    for (int mt = 0; mt < 2; mt++) {
#pragma unroll
        for (int e = 0; e < 2; e++) {
            int r = r0 + wm * 32 + mt * 16 + g + e * 8;
            int w = r / NTOK;  int tok = r - w * NTOK;
#pragma unroll
            for (int nt = 0; nt < 8; nt++) {
                int nc = c0 + wn * 64 + nt * 8 + 2 * t;     // even; pair {nc, nc+1}
                float va0 = acc[mt][nt][e * 2 + 0];
                float va1 = acc[mt][nt][e * 2 + 1];
                if (nc < D_MODEL) {
                    int h = nc >> 5, c = nc & 31;
                    float2 v2 = make_float2(
                        __uint_as_float(f2tf((va0 + __ldg(bq + nc))     * scale)),
                        __uint_as_float(f2tf((va1 + __ldg(bq + nc + 1)) * scale)));
                    *(float2*)(g_q + (((size_t)w * HEADS + h) * NTOK + tok) * DH + c) = v2;
                } else {
                    int kc = nc - D_MODEL;
                    float2 v2 = make_float2(
                        __uint_as_float(f2tf(va0 + __ldg(bkv + kc))),
                        __uint_as_float(f2tf(va1 + __ldg(bkv + kc + 1))));
                    if (kc < D_MODEL) {
                        int h = kc >> 5, c = kc & 31;
                        *(float2*)(g_k + (((size_t)w * HEADS + h) * NTOK + tok) * DH + c) = v2;
                    } else {
                        int vc = kc - D_MODEL;
                        int h = vc >> 5, c = vc & 31;
                        *(float2*)(g_v + (((size_t)w * HEADS + h) * NTOK + tok) * DH + c) = v2;
                    }
                }
            }
        }
    }
}

// ===========================================================================
// Kernel 2: register-resident flash attention. 256 threads / 8 warps /
// 2 CTAs/SM. Pass 1: 8 TRUE pairs (tiles 0..15), one per warp.
// Pass 2 (tail): tiles 16..18 as cheap A-only singles on warps 0..2.
// Per-head bias slice staged in smem; p fed to mma as raw fp32 (HW truncates;
// truncation bias cancels in p/sum).
// ===========================================================================
__global__ __launch_bounds__(256, 2) void attn_flash(const float* __restrict__ bias_table)
{
    extern __shared__ float sm[];
    float* Ks    = sm;                       // NPAD x 36
    float* Vs    = sm + NPAD * QS;           // NPAD x 40
    int*   bJ    = (int*)(Vs + NPAD * VS);   // NPAD
    float* biasS = (float*)(bJ + NPAD);      // NBIAS

    const int wh = blockIdx.x;
    const int w  = wh >> 3, h = wh & 7;
    const int tid = threadIdx.x;
    const int lane = tid & 31, wid = tid >> 5;
    const int g = lane >> 2, t = lane & 3;

    const float* kg = g_k + (size_t)wh * NTOK * DH;
    const float* vg = g_v + (size_t)wh * NTOK * DH;
    for (int idx = tid; idx < NTOK * 8; idx += 256) {
        int row = idx >> 3, q4 = (idx & 7) * 4;
        *(float4*)(Ks + row * QS + q4) = *(const float4*)(kg + row * DH + q4);
        *(float4*)(Vs + row * VS + q4) = *(const float4*)(vg + row * DH + q4);
    }
    for (int idx = tid; idx < (NPAD - NTOK) * 8; idx += 256) {
        int row = NTOK + (idx >> 3), q4 = (idx & 7) * 4;
        float4 z = make_float4(0.f, 0.f, 0.f, 0.f);
        *(float4*)(Ks + row * QS + q4) = z;
        *(float4*)(Vs + row * VS + q4) = z;
    }
    for (int j = tid; j < NPAD; j += 256) {
        int jj = min(j, NTOK - 1);
        int l = jj / 49, r2 = jj - l * 49, a = r2 / 7, b = r2 - a * 7;
        bJ[j] = l * 169 + a * 13 + b;
    }
    for (int i = tid; i < NBIAS; i += 256)
        biasS[i] = __ldg(bias_table + (size_t)i * HEADS + h);
    __syncthreads();

    const float* qg = g_q + (size_t)wh * NTOK * DH;
    const int src1 = (lane & 28) | (t >> 1);
    const int src2 = src1 + 2;

    // ---------------- Pass 1: true pair per warp (tiles 0..15) ----------------
    {
        const int mtA = 2 * wid;
        const int mtB = 2 * wid + 1;

        const int rA0 = mtA * 16 + g, rA1 = rA0 + 8;
        const int rB0 = mtB * 16 + g, rB1 = rB0 + 8;
        // tiles 0..15 cover rows 0..255 < NTOK: no clamping needed
        int CiA0, CiA1, CiB0, CiB1;
        {
            int l, r2, a, b;
            l = rA0 / 49; r2 = rA0 - l * 49; a = r2 / 7; b = r2 - a * 7;
            CiA0 = (l + 5) * 169 + (a + 6) * 13 + (b + 6);
            l = rA1 / 49; r2 = rA1 - l * 49; a = r2 / 7; b = r2 - a * 7;
            CiA1 = (l + 5) * 169 + (a + 6) * 13 + (b + 6);
            l = rB0 / 49; r2 = rB0 - l * 49; a = r2 / 7; b = r2 - a * 7;
            CiB0 = (l + 5) * 169 + (a + 6) * 13 + (b + 6);
            l = rB1 / 49; r2 = rB1 - l * 49; a = r2 / 7; b = r2 - a * 7;
            CiB1 = (l + 5) * 169 + (a + 6) * 13 + (b + 6);
        }

        unsigned qaA[4][4], qaB[4][4];
#pragma unroll
        for (int kk = 0; kk < 4; kk++) {
            qaA[kk][0] = fbits(__ldg(qg + rA0 * DH + kk * 8 + t));
            qaA[kk][1] = fbits(__ldg(qg + rA1 * DH + kk * 8 + t));
            qaA[kk][2] = fbits(__ldg(qg + rA0 * DH + kk * 8 + t + 4));
            qaA[kk][3] = fbits(__ldg(qg + rA1 * DH + kk * 8 + t + 4));
            qaB[kk][0] = fbits(__ldg(qg + rB0 * DH + kk * 8 + t));
            qaB[kk][1] = fbits(__ldg(qg + rB1 * DH + kk * 8 + t));
            qaB[kk][2] = fbits(__ldg(qg + rB0 * DH + kk * 8 + t + 4));
            qaB[kk][3] = fbits(__ldg(qg + rB1 * DH + kk * 8 + t + 4));
        }

        float OA[4][4], OB[4][4];
#pragma unroll
        for (int ot = 0; ot < 4; ot++)
#pragma unroll
            for (int e = 0; e < 4; e++) { OA[ot][e] = 0.f; OB[ot][e] = 0.f; }
        float sA0 = 0.f, sA1 = 0.f, sB0 = 0.f, sB1 = 0.f;

        for (int nt = 0; nt < 37; nt++) {
            float cAx[4] = {0.f, 0.f, 0.f, 0.f}, cAy[4] = {0.f, 0.f, 0.f, 0.f};
            float cBx[4] = {0.f, 0.f, 0.f, 0.f}, cBy[4] = {0.f, 0.f, 0.f, 0.f};
#pragma unroll
            for (int kk = 0; kk < 2; kk++) {
                unsigned b[2];
                b[0] = fbits(Ks[(nt * 8 + g) * QS + kk * 8 + t]);
                b[1] = fbits(Ks[(nt * 8 + g) * QS + kk * 8 + t + 4]);
                mma_tf32(cAx, qaA[kk], b);
                mma_tf32(cBx, qaB[kk], b);
            }
#pragma unroll
            for (int kk = 2; kk < 4; kk++) {
                unsigned b[2];
                b[0] = fbits(Ks[(nt * 8 + g) * QS + kk * 8 + t]);
                b[1] = fbits(Ks[(nt * 8 + g) * QS + kk * 8 + t + 4]);
                mma_tf32(cAy, qaA[kk], b);
                mma_tf32(cBy, qaB[kk], b);
            }

            const int j0 = nt * 8 + 2 * t, j1 = j0 + 1;
            const int bj0 = bJ[j0], bj1 = bJ[j1];
            const bool v0 = (j0 < NTOK), v1 = (j1 < NTOK);

            float pA0 = v0 ? __expf(cAx[0] + cAy[0] + biasS[CiA0 - bj0]) : 0.f;
            float pA1 = v1 ? __expf(cAx[1] + cAy[1] + biasS[CiA0 - bj1]) : 0.f;
            float pA2 = v0 ? __expf(cAx[2] + cAy[2] + biasS[CiA1 - bj0]) : 0.f;
            float pA3 = v1 ? __expf(cAx[3] + cAy[3] + biasS[CiA1 - bj1]) : 0.f;
            float pB0 = v0 ? __expf(cBx[0] + cBy[0] + biasS[CiB0 - bj0]) : 0.f;
            float pB1 = v1 ? __expf(cBx[1] + cBy[1] + biasS[CiB0 - bj1]) : 0.f;
            float pB2 = v0 ? __expf(cBx[2] + cBy[2] + biasS[CiB1 - bj0]) : 0.f;
            float pB3 = v1 ? __expf(cBx[3] + cBy[3] + biasS[CiB1 - bj1]) : 0.f;
            sA0 += pA0 + pA1;  sA1 += pA2 + pA3;
            sB0 += pB0 + pB1;  sB1 += pB2 + pB3;

            // raw fp32 bits into tf32 mma (HW truncates; bias cancels in p/sum)
            unsigned uA0 = fbits(pA0), uA1 = fbits(pA1), uA2 = fbits(pA2), uA3 = fbits(pA3);
            unsigned uB0 = fbits(pB0), uB1 = fbits(pB1), uB2 = fbits(pB2), uB3 = fbits(pB3);

            unsigned paA[4], paB[4];
            {
                unsigned a0 = __shfl_sync(0xffffffffu, uA0, src1);
                unsigned a1 = __shfl_sync(0xffffffffu, uA1, src1);
                unsigned a2 = __shfl_sync(0xffffffffu, uA2, src1);
                unsigned a3 = __shfl_sync(0xffffffffu, uA3, src1);
                unsigned b0 = __shfl_sync(0xffffffffu, uA0, src2);
                unsigned b1 = __shfl_sync(0xffffffffu, uA1, src2);
                unsigned b2 = __shfl_sync(0xffffffffu, uA2, src2);
                unsigned b3 = __shfl_sync(0xffffffffu, uA3, src2);
                paA[0] = (t & 1) ? a1 : a0;
                paA[1] = (t & 1) ? a3 : a2;
                paA[2] = (t & 1) ? b1 : b0;
                paA[3] = (t & 1) ? b3 : b2;
            }
            {
                unsigned a0 = __shfl_sync(0xffffffffu, uB0, src1);
                unsigned a1 = __shfl_sync(0xffffffffu, uB1, src1);
                unsigned a2 = __shfl_sync(0xffffffffu, uB2, src1);
                unsigned a3 = __shfl_sync(0xffffffffu, uB3, src1);
                unsigned b0 = __shfl_sync(0xffffffffu, uB0, src2);
                unsigned b1 = __shfl_sync(0xffffffffu, uB1, src2);
                unsigned b2 = __shfl_sync(0xffffffffu, uB2, src2);
                unsigned b3 = __shfl_sync(0xffffffffu, uB3, src2);
                paB[0] = (t & 1) ? a1 : a0;
                paB[1] = (t & 1) ? a3 : a2;
                paB[2] = (t & 1) ? b1 : b0;
                paB[3] = (t & 1) ? b3 : b2;
            }

#pragma unroll
            for (int ot = 0; ot < 4; ot++) {
                unsigned vb[2];
                vb[0] = fbits(Vs[(nt * 8 + t)     * VS + ot * 8 + g]);
                vb[1] = fbits(Vs[(nt * 8 + t + 4) * VS + ot * 8 + g]);
                mma_tf32(OA[ot], paA, vb);
                mma_tf32(OB[ot], paB, vb);
            }
        }

        sA0 += __shfl_xor_sync(0xffffffffu, sA0, 1);
        sA0 += __shfl_xor_sync(0xffffffffu, sA0, 2);
        sA1 += __shfl_xor_sync(0xffffffffu, sA1, 1);
        sA1 += __shfl_xor_sync(0xffffffffu, sA1, 2);
        sB0 += __shfl_xor_sync(0xffffffffu, sB0, 1);
        sB0 += __shfl_xor_sync(0xffffffffu, sB0, 2);
        sB1 += __shfl_xor_sync(0xffffffffu, sB1, 1);
        sB1 += __shfl_xor_sync(0xffffffffu, sB1, 2);
        const float iA0 = 1.f / sA0, iA1 = 1.f / sA1;
        const float iB0 = 1.f / sB0, iB1 = 1.f / sB1;

        {
            float* d = g_ctx + ((size_t)w * NTOK + rA0) * D_MODEL + h * DH;
#pragma unroll
            for (int ot = 0; ot < 4; ot++)
                *(float2*)(d + ot * 8 + 2 * t) =
                    make_float2(__uint_as_float(f2tf(OA[ot][0] * iA0)),
                                __uint_as_float(f2tf(OA[ot][1] * iA0)));
        }
        {
            float* d = g_ctx + ((size_t)w * NTOK + rA1) * D_MODEL + h * DH;
#pragma unroll
            for (int ot = 0; ot < 4; ot++)
                *(float2*)(d + ot * 8 + 2 * t) =
                    make_float2(__uint_as_float(f2tf(OA[ot][2] * iA1)),
                                __uint_as_float(f2tf(OA[ot][3] * iA1)));
        }
        {
            float* d = g_ctx + ((size_t)w * NTOK + rB0) * D_MODEL + h * DH;
#pragma unroll
            for (int ot = 0; ot < 4; ot++)
                *(float2*)(d + ot * 8 + 2 * t) =
                    make_float2(__uint_as_float(f2tf(OB[ot][0] * iB0)),
                                __uint_as_float(f2tf(OB[ot][1] * iB0)));
        }
        {
            float* d = g_ctx + ((size_t)w * NTOK + rB1) * D_MODEL + h * DH;
#pragma unroll
            for (int ot = 0; ot < 4; ot++)
                *(float2*)(d + ot * 8 + 2 * t) =
                    make_float2(__uint_as_float(f2tf(OB[ot][2] * iB1)),
                                __uint_as_float(f2tf(OB[ot][3] * iB1)));
        }
    }

    // ---------------- Pass 2 (tail): tiles 16..18, A-only, warps 0..2 --------
    if (wid < 3) {
        const int mt = 16 + wid;
        const int r0q = mt * 16 + g, r1q = r0q + 8;
        const int c0q = min(r0q, NTOK - 1), c1q = min(r1q, NTOK - 1);

        int Ci0, Ci1;
        {
            int l, r2, a, b;
            l = c0q / 49; r2 = c0q - l * 49; a = r2 / 7; b = r2 - a * 7;
            Ci0 = (l + 5) * 169 + (a + 6) * 13 + (b + 6);
            l = c1q / 49; r2 = c1q - l * 49; a = r2 / 7; b = r2 - a * 7;
            Ci1 = (l + 5) * 169 + (a + 6) * 13 + (b + 6);
        }

        unsigned qa[4][4];
#pragma unroll
        for (int kk = 0; kk < 4; kk++) {
            qa[kk][0] = fbits(__ldg(qg + c0q * DH + kk * 8 + t));
            qa[kk][1] = fbits(__ldg(qg + c1q * DH + kk * 8 + t));
            qa[kk][2] = fbits(__ldg(qg + c0q * DH + kk * 8 + t + 4));
            qa[kk][3] = fbits(__ldg(qg + c1q * DH + kk * 8 + t + 4));
        }

        float O[4][4];
#pragma unroll
        for (int ot = 0; ot < 4; ot++)
#pragma unroll
            for (int e = 0; e < 4; e++) O[ot][e] = 0.f;
        float s0 = 0.f, s1 = 0.f;

        for (int nt = 0; nt < 37; nt++) {
            float cx[4] = {0.f, 0.f, 0.f, 0.f}, cy[4] = {0.f, 0.f, 0.f, 0.f};
#pragma unroll
            for (int kk = 0; kk < 2; kk++) {
                unsigned b[2];
                b[0] = fbits(Ks[(nt * 8 + g) * QS + kk * 8 + t]);
                b[1] = fbits(Ks[(nt * 8 + g) * QS + kk * 8 + t + 4]);
                mma_tf32(cx, qa[kk], b);
            }
#pragma unroll
            for (int kk = 2; kk < 4; kk++) {
                unsigned b[2];
                b[0] = fbits(Ks[(nt * 8 + g) * QS + kk * 8 + t]);
                b[1] = fbits(Ks[(nt * 8 + g) * QS + kk * 8 + t + 4]);
                mma_tf32(cy, qa[kk], b);
            }

            const int j0 = nt * 8 + 2 * t, j1 = j0 + 1;
            const int bj0 = bJ[j0], bj1 = bJ[j1];
            const bool v0 = (j0 < NTOK), v1 = (j1 < NTOK);

            float p0 = v0 ? __expf(cx[0] + cy[0] + biasS[Ci0 - bj0]) : 0.f;
            float p1 = v1 ? __expf(cx[1] + cy[1] + biasS[Ci0 - bj1]) : 0.f;
            float p2 = v0 ? __expf(cx[2] + cy[2] + biasS[Ci1 - bj0]) : 0.f;
            float p3 = v1 ? __expf(cx[3] + cy[3] + biasS[Ci1 - bj1]) : 0.f;
            s0 += p0 + p1;
            s1 += p2 + p3;

            unsigned u0 = fbits(p0), u1 = fbits(p1), u2 = fbits(p2), u3 = fbits(p3);
            unsigned pa[4];
            {
                unsigned a0 = __shfl_sync(0xffffffffu, u0, src1);
                unsigned a1 = __shfl_sync(0xffffffffu, u1, src1);
                unsigned a2 = __shfl_sync(0xffffffffu, u2, src1);
                unsigned a3 = __shfl_sync(0xffffffffu, u3, src1);
                unsigned b0 = __shfl_sync(0xffffffffu, u0, src2);
                unsigned b1 = __shfl_sync(0xffffffffu, u1, src2);
                unsigned b2 = __shfl_sync(0xffffffffu, u2, src2);
                unsigned b3 = __shfl_sync(0xffffffffu, u3, src2);
                pa[0] = (t & 1) ? a1 : a0;
                pa[1] = (t & 1) ? a3 : a2;
                pa[2] = (t & 1) ? b1 : b0;
                pa[3] = (t & 1) ? b3 : b2;
            }

#pragma unroll
            for (int ot = 0; ot < 4; ot++) {
                unsigned vb[2];
                vb[0] = fbits(Vs[(nt * 8 + t)     * VS + ot * 8 + g]);
                vb[1] = fbits(Vs[(nt * 8 + t + 4) * VS + ot * 8 + g]);
                mma_tf32(O[ot], pa, vb);
            }
        }

        s0 += __shfl_xor_sync(0xffffffffu, s0, 1);
        s0 += __shfl_xor_sync(0xffffffffu, s0, 2);
        s1 += __shfl_xor_sync(0xffffffffu, s1, 1);
        s1 += __shfl_xor_sync(0xffffffffu, s1, 2);
        const float i0 = 1.f / s0, i1 = 1.f / s1;

        if (r0q < NTOK) {
            float* d = g_ctx + ((size_t)w * NTOK + r0q) * D_MODEL + h * DH;
#pragma unroll
            for (int ot = 0; ot < 4; ot++)
                *(float2*)(d + ot * 8 + 2 * t) =
                    make_float2(__uint_as_float(f2tf(O[ot][0] * i0)),
                                __uint_as_float(f2tf(O[ot][1] * i0)));
        }
        if (r1q < NTOK) {
            float* d = g_ctx + ((size_t)w * NTOK + r1q) * D_MODEL + h * DH;
#pragma unroll
            for (int ot = 0; ot < 4; ot++)
                *(float2*)(d + ot * 8 + 2 * t) =
                    make_float2(__uint_as_float(f2tf(O[ot][2] * i1)),
                                __uint_as_float(f2tf(O[ot][3] * i1)));
        }
    }
}

// ===========================================================================
// Kernel 3: output projection. cp.async double-buffer, zero cvts.
// ===========================================================================
__global__ __launch_bounds__(128) void out_gemm_tc(float* __restrict__ out)
{
    __shared__ float As[2][64 * QS];
    __shared__ float Bs[2][32 * BS2];
    __shared__ int   rowbase[64];

    const int tid  = threadIdx.x;
    const int lane = tid & 31, wid = tid >> 5;
    const int wm = wid & 1, wn = wid >> 1;
    const int g = lane >> 2, t = lane & 3;
    const int r0 = blockIdx.y * 64;      // row block (slow dim)
    const int c0 = blockIdx.x * 128;     // col block (fast dim)

    if (tid < 64) rowbase[tid] = x_offset(r0 + tid);
    __syncthreads();

    const float* asrc[4]; unsigned adst[4];
    const float* bsrc[8]; unsigned bdst[8];
#pragma unroll
    for (int i = 0; i < 4; i++) {
        int idx = tid + i * 128;
        int ar = idx >> 3, aq = idx & 7;
        asrc[i] = g_ctx + (size_t)(r0 + ar) * D_MODEL + aq * 4;
        adst[i] = (unsigned)__cvta_generic_to_shared(&As[0][ar * QS + aq * 4]);
    }
#pragma unroll
    for (int i = 0; i < 8; i++) {
        int idx = tid + i * 128;
        int bk = idx >> 5, bc = idx & 31;
        bsrc[i] = g_wout + bk * D_MODEL + c0 + bc * 4;
        bdst[i] = (unsigned)__cvta_generic_to_shared(&Bs[0][bk * BS2 + bc * 4]);
    }
    const unsigned ABYTES = 64 * QS * 4;
    const unsigned BBYTES = 32 * BS2 * 4;

    float acc[2][8][4];
#pragma unroll
    for (int m = 0; m < 2; m++)
#pragma unroll
        for (int n = 0; n < 8; n++)
#pragma unroll
            for (int e = 0; e < 4; e++) acc[m][n][e] = 0.f;

#pragma unroll
    for (int i = 0; i < 4; i++) cp16(adst[i], asrc[i]);
#pragma unroll
    for (int i = 0; i < 8; i++) cp16(bdst[i], bsrc[i]);
    cp_commit();

    for (int it = 0; it < 8; it++) {
        const int cur = it & 1;
        cp_wait0();
        __syncthreads();
        if (it < 7) {
            const int k0 = (it + 1) * 32;
            const unsigned nb = (it + 1) & 1;
#pragma unroll
            for (int i = 0; i < 4; i++) cp16(adst[i] + nb * ABYTES, asrc[i] + k0);
#pragma unroll
            for (int i = 0; i < 8; i++) cp16(bdst[i] + nb * BBYTES, bsrc[i] + (size_t)k0 * D_MODEL);
            cp_commit();
        }
#pragma unroll
        for (int kk = 0; kk < 4; kk++) {
            unsigned afr[2][4];
#pragma unroll
            for (int mt = 0; mt < 2; mt++) {
                int mr = wm * 32 + mt * 16;
                afr[mt][0] = fbits(As[cur][(mr + g)     * QS + kk * 8 + t]);
                afr[mt][1] = fbits(As[cur][(mr + g + 8) * QS + kk * 8 + t]);
                afr[mt][2] = fbits(As[cur][(mr + g)     * QS + kk * 8 + t + 4]);
                afr[mt][3] = fbits(As[cur][(mr + g + 8) * QS + kk * 8 + t + 4]);
            }
#pragma unroll
            for (int nt = 0; nt < 8; nt++) {
                int nc = wn * 64 + nt * 8;
                unsigned bfr[2];
                bfr[0] = fbits(Bs[cur][(kk * 8 + t)     * BS2 + nc + g]);
                bfr[1] = fbits(Bs[cur][(kk * 8 + t + 4) * BS2 + nc + g]);
                mma_tf32(acc[0][nt], afr[0], bfr);
                mma_tf32(acc[1][nt], afr[1], bfr);
            }
        }
    }

#pragma unroll
    for (int mt = 0; mt < 2; mt++) {
#pragma unroll
        for (int e = 0; e < 2; e++) {
            int rl = wm * 32 + mt * 16 + g + e * 8;
            int xb = rowbase[rl];
#pragma unroll
            for (int nt = 0; nt < 8; nt++) {
                int cc = c0 + wn * 64 + nt * 8 + 2 * t;
                *(float2*)(out + xb + cc) =
                    make_float2(acc[mt][nt][e * 2 + 0], acc[mt][nt][e * 2 + 1]);
            }
        }
    }
}

// ---------------------------------------------------------------------------
// Launch
// ---------------------------------------------------------------------------
extern "C" void kernel_launch(void* const* d_in, const int* in_sizes, int n_in,
                              void* d_out, int out_size)
{
    const float* x    = (const float*)d_in[0];
    const float* Wq   = (const float*)d_in[1];
    const float* bq   = (const float*)d_in[2];
    const float* Wkv  = (const float*)d_in[3];
    const float* bkv  = (const float*)d_in[4];
    const float* Wout = (const float*)d_in[5];
    const float* bias = (const float*)d_in[6];
    float* out = (float*)d_out;

    // smem: K + V + bJ + per-head bias slice
    const int attn_smem = (NPAD * QS + NPAD * VS) * 4 + NPAD * 4 + NBIAS * 4;  // 101068 B
    cudaFuncSetAttribute(attn_flash,
                         cudaFuncAttributeMaxDynamicSharedMemorySize, attn_smem);

    conv_w<<<768, 256>>>(Wq, Wkv, Wout);

    dim3 g1(QKV_N / 128, M_ROWS / 64);    // (6, 1323) — cols fast
    qkv_gemm_tc<<<g1, 128>>>(x, bq, bkv);

    attn_flash<<<NWIN * HEADS, 256, attn_smem>>>(bias);

    dim3 g2(D_MODEL / 128, M_ROWS / 64);  // (2, 1323) — cols fast
    out_gemm_tc<<<g2, 128>>>(out);
}

// round 16
// speedup vs baseline: 1.6496x; 1.0302x over previous
#include <cuda_runtime.h>

// ---------------------------------------------------------------------------
// Problem constants
// ---------------------------------------------------------------------------
#define NTOK    294
#define NPAD    304            // padded tokens (19 * 16)
#define NT16    19
#define NWIN    288
#define D_MODEL 256
#define HEADS   8
#define DH      32
#define M_ROWS  (NWIN * NTOK)  // 84672
#define QKV_N   768
#define NBIAS   1859           // (2*6-1)*(2*7-1)*(2*7-1)

// smem strides (floats), conflict-free for the tf32 fragment access patterns
#define QS   36   // K rows (32 cols): banks 4g+t bijective
#define VS   40   // V rows (32 cols): banks 8t+g bijective
#define BS2  136  // GEMM B tile rows (128 cols): banks 8t+g bijective

// ---------------------------------------------------------------------------
// Scratch
// ---------------------------------------------------------------------------
__device__ float g_q   [(size_t)NWIN * HEADS * NTOK * DH];
__device__ float g_k   [(size_t)NWIN * HEADS * NTOK * DH];
__device__ float g_v   [(size_t)NWIN * HEADS * NTOK * DH];
__device__ float g_ctx [(size_t)M_ROWS * D_MODEL];
__device__ float g_wqkv[256 * 768];   // [k][n], tf32 bits
__device__ float g_wout[256 * 256];   // [k][n], tf32 bits

__device__ __forceinline__ int x_offset(int r) {
    int w  = r / NTOK;  int t   = r - w * NTOK;
    int bb = w / 144;   int rem = w - bb * 144;
    int gx = rem / 12;  int gy  = rem - gx * 12;
    int l  = t / 49;    int t2  = t - l * 49;
    int w1 = t2 / 7;    int w2  = t2 - w1 * 7;
    return (((((bb * 6 + l) * 12 + gx) * 12 + gy) * 7 + w1) * 7 + w2) * D_MODEL;
}

__device__ __forceinline__ unsigned f2tf(float f) {
    unsigned u;
    asm("cvt.rna.tf32.f32 %0, %1;" : "=r"(u) : "f"(f));
    return u;
}
__device__ __forceinline__ unsigned fbits(float f) { return __float_as_uint(f); }

__device__ __forceinline__ void mma_tf32(float c[4], const unsigned a[4], const unsigned b[2]) {
    asm volatile(
        "mma.sync.aligned.m16n8k8.row.col.f32.tf32.tf32.f32 "
        "{%0,%1,%2,%3}, {%4,%5,%6,%7}, {%8,%9}, {%0,%1,%2,%3};"
        : "+f"(c[0]), "+f"(c[1]), "+f"(c[2]), "+f"(c[3])
        : "r"(a[0]), "r"(a[1]), "r"(a[2]), "r"(a[3]), "r"(b[0]), "r"(b[1]));
}

__device__ __forceinline__ void cp16(unsigned dst, const void* src) {
    asm volatile("cp.async.cg.shared.global [%0], [%1], 16;" :: "r"(dst), "l"(src));
}
__device__ __forceinline__ void cp_commit() {
    asm volatile("cp.async.commit_group;" ::);
}
__device__ __forceinline__ void cp_wait0() {
    asm volatile("cp.async.wait_group 0;" ::: "memory");
}

// ===========================================================================
// Kernel 0: one-time weight conversion to tf32 ([k][n] layouts).
// ===========================================================================
__global__ __launch_bounds__(256) void conv_w(
    const float* __restrict__ Wq, const float* __restrict__ Wkv,
    const float* __restrict__ Wout)
{
    int idx = blockIdx.x * 256 + threadIdx.x;
    if (idx < 256 * 768) {
        int k = idx / 768, n = idx - k * 768;
        float v = (n < 256) ? Wq[k * 256 + n] : Wkv[k * 512 + (n - 256)];
        g_wqkv[idx] = __uint_as_float(f2tf(v));
    }
    if (idx < 256 * 256) {
        g_wout[idx] = __uint_as_float(f2tf(Wout[idx]));
    }
}

// ===========================================================================
// Kernel 1: QKV projection. CTA 64x128, 4 warps of 32x64, BK=32.
// cp.async double-buffer; x staged RAW (HMMA truncates); weights pre-rounded.
// ===========================================================================
__global__ __launch_bounds__(128) void qkv_gemm_tc(
    const float* __restrict__ x,
    const float* __restrict__ bq, const float* __restrict__ bkv)
{
    __shared__ float As[2][64 * QS];
    __shared__ float Bs[2][32 * BS2];
    __shared__ int   rowbase[64];

    const int tid  = threadIdx.x;
    const int lane = tid & 31, wid = tid >> 5;
    const int wm = wid & 1, wn = wid >> 1;
    const int g = lane >> 2, t = lane & 3;
    const int r0 = blockIdx.y * 64;      // row block (slow dim)
    const int c0 = blockIdx.x * 128;     // col block (fast dim)

    if (tid < 64) rowbase[tid] = x_offset(r0 + tid);
    __syncthreads();

    const float* asrc[4]; unsigned adst[4];
    const float* bsrc[8]; unsigned bdst[8];
#pragma unroll
    for (int i = 0; i < 4; i++) {
        int idx = tid + i * 128;
        int ar = idx >> 3, aq = idx & 7;
        asrc[i] = x + rowbase[ar] + aq * 4;
        adst[i] = (unsigned)__cvta_generic_to_shared(&As[0][ar * QS + aq * 4]);
    }
#pragma unroll
    for (int i = 0; i < 8; i++) {
        int idx = tid + i * 128;
        int bk = idx >> 5, bc = idx & 31;
        bsrc[i] = g_wqkv + bk * QKV_N + c0 + bc * 4;
        bdst[i] = (unsigned)__cvta_generic_to_shared(&Bs[0][bk * BS2 + bc * 4]);
    }
    const unsigned ABYTES = 64 * QS * 4;
    const unsigned BBYTES = 32 * BS2 * 4;

    float acc[2][8][4];
#pragma unroll
    for (int m = 0; m < 2; m++)
#pragma unroll
        for (int n = 0; n < 8; n++)
#pragma unroll
            for (int e = 0; e < 4; e++) acc[m][n][e] = 0.f;

#pragma unroll
    for (int i = 0; i < 4; i++) cp16(adst[i], asrc[i]);
#pragma unroll
    for (int i = 0; i < 8; i++) cp16(bdst[i], bsrc[i]);
    cp_commit();

    for (int it = 0; it < 8; it++) {
        const int cur = it & 1;
        cp_wait0();
        __syncthreads();
        if (it < 7) {
            const int k0 = (it + 1) * 32;
            const unsigned nb = (it + 1) & 1;
#pragma unroll
            for (int i = 0; i < 4; i++) cp16(adst[i] + nb * ABYTES, asrc[i] + k0);
#pragma unroll
            for (int i = 0; i < 8; i++) cp16(bdst[i] + nb * BBYTES, bsrc[i] + (size_t)k0 * QKV_N);
            cp_commit();
        }
#pragma unroll
        for (int kk = 0; kk < 4; kk++) {
            unsigned afr[2][4];
#pragma unroll
            for (int mt = 0; mt < 2; mt++) {
                int mr = wm * 32 + mt * 16;
                afr[mt][0] = fbits(As[cur][(mr + g)     * QS + kk * 8 + t]);
                afr[mt][1] = fbits(As[cur][(mr + g + 8) * QS + kk * 8 + t]);
                afr[mt][2] = fbits(As[cur][(mr + g)     * QS + kk * 8 + t + 4]);
                afr[mt][3] = fbits(As[cur][(mr + g + 8) * QS + kk * 8 + t + 4]);
            }
#pragma unroll
            for (int nt = 0; nt < 8; nt++) {
                int nc = wn * 64 + nt * 8;
                unsigned bfr[2];
                bfr[0] = fbits(Bs[cur][(kk * 8 + t)     * BS2 + nc + g]);
                bfr[1] = fbits(Bs[cur][(kk * 8 + t + 4) * BS2 + nc + g]);
                mma_tf32(acc[0][nt], afr[0], bfr);
                mma_tf32(acc[1][nt], afr[1], bfr);
            }
        }
    }

    const float scale = 0.17677669529663687f;
#pragma unroll
    for (int mt = 0; mt < 2; mt++) {
#pragma unroll
        for (int e = 0; e < 2; e++) {
            int r = r0 + wm * 32 + mt * 16 + g + e * 8;
            int w = r / NTOK;  int tok = r - w * NTOK;
#pragma unroll
            for (int nt = 0; nt < 8; nt++) {
                int nc = c0 + wn * 64 + nt * 8 + 2 * t;     // even; pair {nc, nc+1}
                float va0 = acc[mt][nt][e * 2 + 0];
                float va1 = acc[mt][nt][e * 2 + 1];
                if (nc < D_MODEL) {
                    int h = nc >> 5, c = nc & 31;
                    float2 v2 = make_float2(
                        __uint_as_float(f2tf((va0 + __ldg(bq + nc))     * scale)),
                        __uint_as_float(f2tf((va1 + __ldg(bq + nc + 1)) * scale)));
                    *(float2*)(g_q + (((size_t)w * HEADS + h) * NTOK + tok) * DH + c) = v2;
                } else {
                    int kc = nc - D_MODEL;
                    float2 v2 = make_float2(
                        __uint_as_float(f2tf(va0 + __ldg(bkv + kc))),
                        __uint_as_float(f2tf(va1 + __ldg(bkv + kc + 1))));
                    if (kc < D_MODEL) {
                        int h = kc >> 5, c = kc & 31;
                        *(float2*)(g_k + (((size_t)w * HEADS + h) * NTOK + tok) * DH + c) = v2;
                    } else {
                        int vc = kc - D_MODEL;
                        int h = vc >> 5, c = vc & 31;
                        *(float2*)(g_v + (((size_t)w * HEADS + h) * NTOK + tok) * DH + c) = v2;
                    }
                }
            }
        }
    }
}

// ===========================================================================
// Kernel 2: register-resident flash attention. 256 threads / 8 warps /
// 2 CTAs/SM.
// Pass 1: 8 TRUE pairs (tiles 0..15), one per warp.
// Pass 2: tail tiles 16..18 split by KEY-HALF across 6 warps; partials
// combined via smem atomicAdd (exactly 2 addends per slot -> deterministic,
// since this softmax needs no running max). 3 warps normalize + store.
// ===========================================================================
__global__ __launch_bounds__(256, 2) void attn_flash(const float* __restrict__ bias_table)
{
    extern __shared__ float sm[];
    float* Ks    = sm;                       // NPAD x 36
    float* Vs    = sm + NPAD * QS;           // NPAD x 40
    int*   bJ    = (int*)(Vs + NPAD * VS);   // NPAD
    float* biasS = (float*)(bJ + NPAD);      // NBIAS
    float* slabO = biasS + NBIAS;            // 3 * 512 (tail O partials)
    float* slabS = slabO + 3 * 512;          // 3 * 16  (tail row sums)

    const int wh = blockIdx.x;
    const int w  = wh >> 3, h = wh & 7;
    const int tid = threadIdx.x;
    const int lane = tid & 31, wid = tid >> 5;
    const int g = lane >> 2, t = lane & 3;

    const float* kg = g_k + (size_t)wh * NTOK * DH;
    const float* vg = g_v + (size_t)wh * NTOK * DH;
    for (int idx = tid; idx < NTOK * 8; idx += 256) {
        int row = idx >> 3, q4 = (idx & 7) * 4;
        *(float4*)(Ks + row * QS + q4) = *(const float4*)(kg + row * DH + q4);
        *(float4*)(Vs + row * VS + q4) = *(const float4*)(vg + row * DH + q4);
    }
    for (int idx = tid; idx < (NPAD - NTOK) * 8; idx += 256) {
        int row = NTOK + (idx >> 3), q4 = (idx & 7) * 4;
        float4 z = make_float4(0.f, 0.f, 0.f, 0.f);
        *(float4*)(Ks + row * QS + q4) = z;
        *(float4*)(Vs + row * VS + q4) = z;
    }
    for (int j = tid; j < NPAD; j += 256) {
        int jj = min(j, NTOK - 1);
        int l = jj / 49, r2 = jj - l * 49, a = r2 / 7, b = r2 - a * 7;
        bJ[j] = l * 169 + a * 13 + b;
    }
    for (int i = tid; i < NBIAS; i += 256)
        biasS[i] = __ldg(bias_table + (size_t)i * HEADS + h);
    for (int i = tid; i < 3 * 512 + 48; i += 256)
        slabO[i] = 0.f;                      // zero partial slabs (+ sums)
    __syncthreads();

    const float* qg = g_q + (size_t)wh * NTOK * DH;
    const int src1 = (lane & 28) | (t >> 1);
    const int src2 = src1 + 2;

    // ---------------- Pass 1: true pair per warp (tiles 0..15) ----------------
    {
        const int mtA = 2 * wid;
        const int mtB = 2 * wid + 1;

        const int rA0 = mtA * 16 + g, rA1 = rA0 + 8;
        const int rB0 = mtB * 16 + g, rB1 = rB0 + 8;
        int CiA0, CiA1, CiB0, CiB1;
        {
            int l, r2, a, b;
            l = rA0 / 49; r2 = rA0 - l * 49; a = r2 / 7; b = r2 - a * 7;
            CiA0 = (l + 5) * 169 + (a + 6) * 13 + (b + 6);
            l = rA1 / 49; r2 = rA1 - l * 49; a = r2 / 7; b = r2 - a * 7;
            CiA1 = (l + 5) * 169 + (a + 6) * 13 + (b + 6);
            l = rB0 / 49; r2 = rB0 - l * 49; a = r2 / 7; b = r2 - a * 7;
            CiB0 = (l + 5) * 169 + (a + 6) * 13 + (b + 6);
            l = rB1 / 49; r2 = rB1 - l * 49; a = r2 / 7; b = r2 - a * 7;
            CiB1 = (l + 5) * 169 + (a + 6) * 13 + (b + 6);
        }

        unsigned qaA[4][4], qaB[4][4];
#pragma unroll
        for (int kk = 0; kk < 4; kk++) {
            qaA[kk][0] = fbits(__ldg(qg + rA0 * DH + kk * 8 + t));
            qaA[kk][1] = fbits(__ldg(qg + rA1 * DH + kk * 8 + t));
            qaA[kk][2] = fbits(__ldg(qg + rA0 * DH + kk * 8 + t + 4));
            qaA[kk][3] = fbits(__ldg(qg + rA1 * DH + kk * 8 + t + 4));
            qaB[kk][0] = fbits(__ldg(qg + rB0 * DH + kk * 8 + t));
            qaB[kk][1] = fbits(__ldg(qg + rB1 * DH + kk * 8 + t));
            qaB[kk][2] = fbits(__ldg(qg + rB0 * DH + kk * 8 + t + 4));
            qaB[kk][3] = fbits(__ldg(qg + rB1 * DH + kk * 8 + t + 4));
        }

        float OA[4][4], OB[4][4];
#pragma unroll
        for (int ot = 0; ot < 4; ot++)
#pragma unroll
            for (int e = 0; e < 4; e++) { OA[ot][e] = 0.f; OB[ot][e] = 0.f; }
        float sA0 = 0.f, sA1 = 0.f, sB0 = 0.f, sB1 = 0.f;

        for (int nt = 0; nt < 37; nt++) {
            float cAx[4] = {0.f, 0.f, 0.f, 0.f}, cAy[4] = {0.f, 0.f, 0.f, 0.f};
            float cBx[4] = {0.f, 0.f, 0.f, 0.f}, cBy[4] = {0.f, 0.f, 0.f, 0.f};
#pragma unroll
            for (int kk = 0; kk < 2; kk++) {
                unsigned b[2];
                b[0] = fbits(Ks[(nt * 8 + g) * QS + kk * 8 + t]);
                b[1] = fbits(Ks[(nt * 8 + g) * QS + kk * 8 + t + 4]);
                mma_tf32(cAx, qaA[kk], b);
                mma_tf32(cBx, qaB[kk], b);
            }
#pragma unroll
            for (int kk = 2; kk < 4; kk++) {
                unsigned b[2];
                b[0] = fbits(Ks[(nt * 8 + g) * QS + kk * 8 + t]);
                b[1] = fbits(Ks[(nt * 8 + g) * QS + kk * 8 + t + 4]);
                mma_tf32(cAy, qaA[kk], b);
                mma_tf32(cBy, qaB[kk], b);
            }

            const int j0 = nt * 8 + 2 * t, j1 = j0 + 1;
            const int bj0 = bJ[j0], bj1 = bJ[j1];
            const bool v0 = (j0 < NTOK), v1 = (j1 < NTOK);

            float pA0 = v0 ? __expf(cAx[0] + cAy[0] + biasS[CiA0 - bj0]) : 0.f;
            float pA1 = v1 ? __expf(cAx[1] + cAy[1] + biasS[CiA0 - bj1]) : 0.f;
            float pA2 = v0 ? __expf(cAx[2] + cAy[2] + biasS[CiA1 - bj0]) : 0.f;
            float pA3 = v1 ? __expf(cAx[3] + cAy[3] + biasS[CiA1 - bj1]) : 0.f;
            float pB0 = v0 ? __expf(cBx[0] + cBy[0] + biasS[CiB0 - bj0]) : 0.f;
            float pB1 = v1 ? __expf(cBx[1] + cBy[1] + biasS[CiB0 - bj1]) : 0.f;
            float pB2 = v0 ? __expf(cBx[2] + cBy[2] + biasS[CiB1 - bj0]) : 0.f;
            float pB3 = v1 ? __expf(cBx[3] + cBy[3] + biasS[CiB1 - bj1]) : 0.f;
            sA0 += pA0 + pA1;  sA1 += pA2 + pA3;
            sB0 += pB0 + pB1;  sB1 += pB2 + pB3;

            unsigned uA0 = fbits(pA0), uA1 = fbits(pA1), uA2 = fbits(pA2), uA3 = fbits(pA3);
            unsigned uB0 = fbits(pB0), uB1 = fbits(pB1), uB2 = fbits(pB2), uB3 = fbits(pB3);

            unsigned paA[4], paB[4];
            {
                unsigned a0 = __shfl_sync(0xffffffffu, uA0, src1);
                unsigned a1 = __shfl_sync(0xffffffffu, uA1, src1);
                unsigned a2 = __shfl_sync(0xffffffffu, uA2, src1);
                unsigned a3 = __shfl_sync(0xffffffffu, uA3, src1);
                unsigned b0 = __shfl_sync(0xffffffffu, uA0, src2);
                unsigned b1 = __shfl_sync(0xffffffffu, uA1, src2);
                unsigned b2 = __shfl_sync(0xffffffffu, uA2, src2);
                unsigned b3 = __shfl_sync(0xffffffffu, uA3, src2);
                paA[0] = (t & 1) ? a1 : a0;
                paA[1] = (t & 1) ? a3 : a2;
                paA[2] = (t & 1) ? b1 : b0;
                paA[3] = (t & 1) ? b3 : b2;
            }
            {
                unsigned a0 = __shfl_sync(0xffffffffu, uB0, src1);
                unsigned a1 = __shfl_sync(0xffffffffu, uB1, src1);
                unsigned a2 = __shfl_sync(0xffffffffu, uB2, src1);
                unsigned a3 = __shfl_sync(0xffffffffu, uB3, src1);
                unsigned b0 = __shfl_sync(0xffffffffu, uB0, src2);
                unsigned b1 = __shfl_sync(0xffffffffu, uB1, src2);
                unsigned b2 = __shfl_sync(0xffffffffu, uB2, src2);
                unsigned b3 = __shfl_sync(0xffffffffu, uB3, src2);
                paB[0] = (t & 1) ? a1 : a0;
                paB[1] = (t & 1) ? a3 : a2;
                paB[2] = (t & 1) ? b1 : b0;
                paB[3] = (t & 1) ? b3 : b2;
            }

#pragma unroll
            for (int ot = 0; ot < 4; ot++) {
                unsigned vb[2];
                vb[0] = fbits(Vs[(nt * 8 + t)     * VS + ot * 8 + g]);
                vb[1] = fbits(Vs[(nt * 8 + t + 4) * VS + ot * 8 + g]);
                mma_tf32(OA[ot], paA, vb);
                mma_tf32(OB[ot], paB, vb);
            }
        }

        sA0 += __shfl_xor_sync(0xffffffffu, sA0, 1);
        sA0 += __shfl_xor_sync(0xffffffffu, sA0, 2);
        sA1 += __shfl_xor_sync(0xffffffffu, sA1, 1);
        sA1 += __shfl_xor_sync(0xffffffffu, sA1, 2);
        sB0 += __shfl_xor_sync(0xffffffffu, sB0, 1);
        sB0 += __shfl_xor_sync(0xffffffffu, sB0, 2);
        sB1 += __shfl_xor_sync(0xffffffffu, sB1, 1);
        sB1 += __shfl_xor_sync(0xffffffffu, sB1, 2);
        const float iA0 = 1.f / sA0, iA1 = 1.f / sA1;
        const float iB0 = 1.f / sB0, iB1 = 1.f / sB1;

        {
            float* d = g_ctx + ((size_t)w * NTOK + rA0) * D_MODEL + h * DH;
#pragma unroll
            for (int ot = 0; ot < 4; ot++)
                *(float2*)(d + ot * 8 + 2 * t) =
                    make_float2(__uint_as_float(f2tf(OA[ot][0] * iA0)),
                                __uint_as_float(f2tf(OA[ot][1] * iA0)));
        }
        {
            float* d = g_ctx + ((size_t)w * NTOK + rA1) * D_MODEL + h * DH;
#pragma unroll
            for (int ot = 0; ot < 4; ot++)
                *(float2*)(d + ot * 8 + 2 * t) =
                    make_float2(__uint_as_float(f2tf(OA[ot][2] * iA1)),
                                __uint_as_float(f2tf(OA[ot][3] * iA1)));
        }
        {
            float* d = g_ctx + ((size_t)w * NTOK + rB0) * D_MODEL + h * DH;
#pragma unroll
            for (int ot = 0; ot < 4; ot++)
                *(float2*)(d + ot * 8 + 2 * t) =
                    make_float2(__uint_as_float(f2tf(OB[ot][0] * iB0)),
                                __uint_as_float(f2tf(OB[ot][1] * iB0)));
        }
        {
            float* d = g_ctx + ((size_t)w * NTOK + rB1) * D_MODEL + h * DH;
#pragma unroll
            for (int ot = 0; ot < 4; ot++)
                *(float2*)(d + ot * 8 + 2 * t) =
                    make_float2(__uint_as_float(f2tf(OB[ot][2] * iB1)),
                                __uint_as_float(f2tf(OB[ot][3] * iB1)));
        }
    }

    // ------- Pass 2: tail tiles 16..18 split by key-half over 6 warps -------
    if (wid < 6) {
        const int tt   = wid >> 1;           // 0..2 -> tile 16+tt
        const int half = wid & 1;
        const int ntLo = half ? 19 : 0;
        const int ntHi = half ? 37 : 19;
        const int mt = 16 + tt;
        const int r0q = mt * 16 + g, r1q = r0q + 8;
        const int c0q = min(r0q, NTOK - 1), c1q = min(r1q, NTOK - 1);

        int Ci0, Ci1;
        {
            int l, r2, a, b;
            l = c0q / 49; r2 = c0q - l * 49; a = r2 / 7; b = r2 - a * 7;
            Ci0 = (l + 5) * 169 + (a + 6) * 13 + (b + 6);
            l = c1q / 49; r2 = c1q - l * 49; a = r2 / 7; b = r2 - a * 7;
            Ci1 = (l + 5) * 169 + (a + 6) * 13 + (b + 6);
        }

        unsigned qa[4][4];
#pragma unroll
        for (int kk = 0; kk < 4; kk++) {
            qa[kk][0] = fbits(__ldg(qg + c0q * DH + kk * 8 + t));
            qa[kk][1] = fbits(__ldg(qg + c1q * DH + kk * 8 + t));
            qa[kk][2] = fbits(__ldg(qg + c0q * DH + kk * 8 + t + 4));
            qa[kk][3] = fbits(__ldg(qg + c1q * DH + kk * 8 + t + 4));
        }

        float O[4][4];
#pragma unroll
        for (int ot = 0; ot < 4; ot++)
#pragma unroll
            for (int e = 0; e < 4; e++) O[ot][e] = 0.f;
        float s0 = 0.f, s1 = 0.f;

        for (int nt = ntLo; nt < ntHi; nt++) {
            float cx[4] = {0.f, 0.f, 0.f, 0.f}, cy[4] = {0.f, 0.f, 0.f, 0.f};
#pragma unroll
            for (int kk = 0; kk < 2; kk++) {
                unsigned b[2];
                b[0] = fbits(Ks[(nt * 8 + g) * QS + kk * 8 + t]);
                b[1] = fbits(Ks[(nt * 8 + g) * QS + kk * 8 + t + 4]);
                mma_tf32(cx, qa[kk], b);
            }
#pragma unroll
            for (int kk = 2; kk < 4; kk++) {
                unsigned b[2];
                b[0] = fbits(Ks[(nt * 8 + g) * QS + kk * 8 + t]);
                b[1] = fbits(Ks[(nt * 8 + g) * QS + kk * 8 + t + 4]);
                mma_tf32(cy, qa[kk], b);
            }

            const int j0 = nt * 8 + 2 * t, j1 = j0 + 1;
            const int bj0 = bJ[j0], bj1 = bJ[j1];
            const bool v0 = (j0 < NTOK), v1 = (j1 < NTOK);

            float p0 = v0 ? __expf(cx[0] + cy[0] + biasS[Ci0 - bj0]) : 0.f;
            float p1 = v1 ? __expf(cx[1] + cy[1] + biasS[Ci0 - bj1]) : 0.f;
            float p2 = v0 ? __expf(cx[2] + cy[2] + biasS[Ci1 - bj0]) : 0.f;
            float p3 = v1 ? __expf(cx[3] + cy[3] + biasS[Ci1 - bj1]) : 0.f;
            s0 += p0 + p1;
            s1 += p2 + p3;

            unsigned u0 = fbits(p0), u1 = fbits(p1), u2 = fbits(p2), u3 = fbits(p3);
            unsigned pa[4];
            {
                unsigned a0 = __shfl_sync(0xffffffffu, u0, src1);
                unsigned a1 = __shfl_sync(0xffffffffu, u1, src1);
                unsigned a2 = __shfl_sync(0xffffffffu, u2, src1);
                unsigned a3 = __shfl_sync(0xffffffffu, u3, src1);
                unsigned b0 = __shfl_sync(0xffffffffu, u0, src2);
                unsigned b1 = __shfl_sync(0xffffffffu, u1, src2);
                unsigned b2 = __shfl_sync(0xffffffffu, u2, src2);
                unsigned b3 = __shfl_sync(0xffffffffu, u3, src2);
                pa[0] = (t & 1) ? a1 : a0;
                pa[1] = (t & 1) ? a3 : a2;
                pa[2] = (t & 1) ? b1 : b0;
                pa[3] = (t & 1) ? b3 : b2;
            }

#pragma unroll
            for (int ot = 0; ot < 4; ot++) {
                unsigned vb[2];
                vb[0] = fbits(Vs[(nt * 8 + t)     * VS + ot * 8 + g]);
                vb[1] = fbits(Vs[(nt * 8 + t + 4) * VS + ot * 8 + g]);
                mma_tf32(O[ot], pa, vb);
            }
        }

        // reduce sums within the 4-lane t-group, then one atomicAdd per row
        s0 += __shfl_xor_sync(0xffffffffu, s0, 1);
        s0 += __shfl_xor_sync(0xffffffffu, s0, 2);
        s1 += __shfl_xor_sync(0xffffffffu, s1, 1);
        s1 += __shfl_xor_sync(0xffffffffu, s1, 2);

        float* slab = slabO + tt * 512;
        // O partials: each (row, col) slot receives exactly 2 atomic adds
        // (one per key-half) -> fp32-commutative -> deterministic.
#pragma unroll
        for (int ot = 0; ot < 4; ot++) {
            atomicAdd(&slab[g * 32 + ot * 8 + 2 * t],           O[ot][0]);
            atomicAdd(&slab[g * 32 + ot * 8 + 2 * t + 1],       O[ot][1]);
            atomicAdd(&slab[(g + 8) * 32 + ot * 8 + 2 * t],     O[ot][2]);
            atomicAdd(&slab[(g + 8) * 32 + ot * 8 + 2 * t + 1], O[ot][3]);
        }
        if (t == 0) {
            atomicAdd(&slabS[tt * 16 + g],     s0);
            atomicAdd(&slabS[tt * 16 + g + 8], s1);
        }
    }
    __syncthreads();

    // ------- Tail merge: 3 warps normalize + store tiles 16..18 -------
    if (wid < 3) {
        const int mt = 16 + wid;
        const int r0q = mt * 16 + g, r1q = r0q + 8;
        const float* slab = slabO + wid * 512;
        const float i0 = 1.f / slabS[wid * 16 + g];
        const float i1 = 1.f / slabS[wid * 16 + g + 8];

        if (r0q < NTOK) {
            float* d = g_ctx + ((size_t)w * NTOK + r0q) * D_MODEL + h * DH;
#pragma unroll
            for (int ot = 0; ot < 4; ot++) {
                float o0 = slab[g * 32 + ot * 8 + 2 * t];
                float o1 = slab[g * 32 + ot * 8 + 2 * t + 1];
                *(float2*)(d + ot * 8 + 2 * t) =
                    make_float2(__uint_as_float(f2tf(o0 * i0)),
                                __uint_as_float(f2tf(o1 * i0)));
            }
        }
        if (r1q < NTOK) {
            float* d = g_ctx + ((size_t)w * NTOK + r1q) * D_MODEL + h * DH;
#pragma unroll
            for (int ot = 0; ot < 4; ot++) {
                float o0 = slab[(g + 8) * 32 + ot * 8 + 2 * t];
                float o1 = slab[(g + 8) * 32 + ot * 8 + 2 * t + 1];
                *(float2*)(d + ot * 8 + 2 * t) =
                    make_float2(__uint_as_float(f2tf(o0 * i1)),
                                __uint_as_float(f2tf(o1 * i1)));
            }
        }
    }
}

// ===========================================================================
// Kernel 3: output projection. cp.async double-buffer, zero cvts.
// ===========================================================================
__global__ __launch_bounds__(128) void out_gemm_tc(float* __restrict__ out)
{
    __shared__ float As[2][64 * QS];
    __shared__ float Bs[2][32 * BS2];
    __shared__ int   rowbase[64];

    const int tid  = threadIdx.x;
    const int lane = tid & 31, wid = tid >> 5;
    const int wm = wid & 1, wn = wid >> 1;
    const int g = lane >> 2, t = lane & 3;
    const int r0 = blockIdx.y * 64;      // row block (slow dim)
    const int c0 = blockIdx.x * 128;     // col block (fast dim)

    if (tid < 64) rowbase[tid] = x_offset(r0 + tid);
    __syncthreads();

    const float* asrc[4]; unsigned adst[4];
    const float* bsrc[8]; unsigned bdst[8];
#pragma unroll
    for (int i = 0; i < 4; i++) {
        int idx = tid + i * 128;
        int ar = idx >> 3, aq = idx & 7;
        asrc[i] = g_ctx + (size_t)(r0 + ar) * D_MODEL + aq * 4;
        adst[i] = (unsigned)__cvta_generic_to_shared(&As[0][ar * QS + aq * 4]);
    }
#pragma unroll
    for (int i = 0; i < 8; i++) {
        int idx = tid + i * 128;
        int bk = idx >> 5, bc = idx & 31;
        bsrc[i] = g_wout + bk * D_MODEL + c0 + bc * 4;
        bdst[i] = (unsigned)__cvta_generic_to_shared(&Bs[0][bk * BS2 + bc * 4]);
    }
    const unsigned ABYTES = 64 * QS * 4;
    const unsigned BBYTES = 32 * BS2 * 4;

    float acc[2][8][4];
#pragma unroll
    for (int m = 0; m < 2; m++)
#pragma unroll
        for (int n = 0; n < 8; n++)
#pragma unroll
            for (int e = 0; e < 4; e++) acc[m][n][e] = 0.f;

#pragma unroll
    for (int i = 0; i < 4; i++) cp16(adst[i], asrc[i]);
#pragma unroll
    for (int i = 0; i < 8; i++) cp16(bdst[i], bsrc[i]);
    cp_commit();

    for (int it = 0; it < 8; it++) {
        const int cur = it & 1;
        cp_wait0();
        __syncthreads();
        if (it < 7) {
            const int k0 = (it + 1) * 32;
            const unsigned nb = (it + 1) & 1;
#pragma unroll
            for (int i = 0; i < 4; i++) cp16(adst[i] + nb * ABYTES, asrc[i] + k0);
#pragma unroll
            for (int i = 0; i < 8; i++) cp16(bdst[i] + nb * BBYTES, bsrc[i] + (size_t)k0 * D_MODEL);
            cp_commit();
        }
#pragma unroll
        for (int kk = 0; kk < 4; kk++) {
            unsigned afr[2][4];
#pragma unroll
            for (int mt = 0; mt < 2; mt++) {
                int mr = wm * 32 + mt * 16;
                afr[mt][0] = fbits(As[cur][(mr + g)     * QS + kk * 8 + t]);
                afr[mt][1] = fbits(As[cur][(mr + g + 8) * QS + kk * 8 + t]);
                afr[mt][2] = fbits(As[cur][(mr + g)     * QS + kk * 8 + t + 4]);
                afr[mt][3] = fbits(As[cur][(mr + g + 8) * QS + kk * 8 + t + 4]);
            }
#pragma unroll
            for (int nt = 0; nt < 8; nt++) {
                int nc = wn * 64 + nt * 8;
                unsigned bfr[2];
                bfr[0] = fbits(Bs[cur][(kk * 8 + t)     * BS2 + nc + g]);
                bfr[1] = fbits(Bs[cur][(kk * 8 + t + 4) * BS2 + nc + g]);
                mma_tf32(acc[0][nt], afr[0], bfr);
                mma_tf32(acc[1][nt], afr[1], bfr);
            }
        }
    }

#pragma unroll
    for (int mt = 0; mt < 2; mt++) {
#pragma unroll
        for (int e = 0; e < 2; e++) {
            int rl = wm * 32 + mt * 16 + g + e * 8;
            int xb = rowbase[rl];
#pragma unroll
            for (int nt = 0; nt < 8; nt++) {
                int cc = c0 + wn * 64 + nt * 8 + 2 * t;
                *(float2*)(out + xb + cc) =
                    make_float2(acc[mt][nt][e * 2 + 0], acc[mt][nt][e * 2 + 1]);
            }
        }
    }
}

// ---------------------------------------------------------------------------
// Launch
// ---------------------------------------------------------------------------
extern "C" void kernel_launch(void* const* d_in, const int* in_sizes, int n_in,
                              void* d_out, int out_size)
{
    const float* x    = (const float*)d_in[0];
    const float* Wq   = (const float*)d_in[1];
    const float* bq   = (const float*)d_in[2];
    const float* Wkv  = (const float*)d_in[3];
    const float* bkv  = (const float*)d_in[4];
    const float* Wout = (const float*)d_in[5];
    const float* bias = (const float*)d_in[6];
    float* out = (float*)d_out;

    // smem: K + V + bJ + per-head bias slice + tail partial slabs
    const int attn_smem = (NPAD * QS + NPAD * VS) * 4 + NPAD * 4 + NBIAS * 4
                        + (3 * 512 + 48) * 4;   // 107404 B (2 CTAs/SM)
    cudaFuncSetAttribute(attn_flash,
                         cudaFuncAttributeMaxDynamicSharedMemorySize, attn_smem);

    conv_w<<<768, 256>>>(Wq, Wkv, Wout);

    dim3 g1(QKV_N / 128, M_ROWS / 64);    // (6, 1323) — cols fast
    qkv_gemm_tc<<<g1, 128>>>(x, bq, bkv);

    attn_flash<<<NWIN * HEADS, 256, attn_smem>>>(bias);

    dim3 g2(D_MODEL / 128, M_ROWS / 64);  // (2, 1323) — cols fast
    out_gemm_tc<<<g2, 128>>>(out);
}